// round 13
// baseline (speedup 1.0000x reference)
#include <cuda_runtime.h>
#include <cuda_bf16.h>
#include <math.h>
#include <stdint.h>

// ---------------- problem constants ----------------
#define BATCH   2
#define CIN     128
#define COUT    512
#define DD      8
#define HH      32
#define WW      32
#define POS     (DD*HH*WW)          // 8192
#define NCOL    (BATCH*POS)         // 16384
#define KDIM    (CIN*27)            // 3456
#define NANCH   9
#define NPROP   (POS*NANCH)         // 73728 per batch
#define PRE_NMS 2048
#define POST_NMS 300
#define NMS_TH  0.7f
#define HROWS   72
#define CLSROWS 18
#define MARGIN  2e-3f
#define CCAP    8192
#define CW      8192

// emu conv tiling (A bf16 x B bf16x2), K reordered as (off, c); swizzled smem
#define TILE_K    32
#define KITERS    (KDIM/TILE_K)     // 108
#define PLANE_W   (128*16)          // 2048 words (no padding; XOR swizzle)
#define STAGE_W   (3*PLANE_W)       // A, B1, B2
#define STAGE_B   (STAGE_W*4)       // 24576 bytes
#define NSTG      3
#define SMEM_EMU  (NSTG*STAGE_B)    // 73728 -> 3 CTAs/SM

// swizzled word index: logical word qd*4+qc of row r
#define SWIDX(r, qd, qc) ((r)*16 + ((((qd)) ^ (((r)>>1)&3))<<2) + (qc))

// padded transposed feature map: [B][D+2][H+2][W+2][C]
#define FPD     (DD+2)
#define FPH     (HH+2)
#define FPW     (WW+2)
#define FPAD    ((size_t)BATCH*FPD*FPH*FPW*CIN)

// ---------------- static scratch ----------------
__device__ __align__(128) __nv_bfloat16 g_fp1[FPAD];
__device__ __align__(128) __nv_bfloat16 g_fp2[FPAD];
__device__ __align__(128) __nv_bfloat16 g_ar [(size_t)COUT * KDIM];
__device__ float g_xe  [(size_t)COUT * NCOL];
__device__ float g_h   [(size_t)CLSROWS * NCOL];
__device__ float g_colc[(size_t)KDIM * CW];
__device__ float g_xc  [(size_t)COUT * CW];
__device__ float g_hc  [(size_t)HROWS * CW];
__device__ float g_wh  [HROWS * 512];
__device__ float g_bh  [HROWS];
__device__ float g_escore[BATCH * NPROP];
__device__ float g_thr[BATCH];
__device__ int   g_pflag[BATCH * POS];
__device__ int   g_plist[CCAP];
__device__ int   g_nc[4];
__device__ float g_scores[BATCH * NPROP];
__device__ float g_boxes [(size_t)BATCH * NPROP * 6];
__device__ unsigned long long g_cand[BATCH][4096];
__device__ float g_sboxes[(size_t)BATCH * PRE_NMS * 6];
__device__ unsigned long long g_mask[(size_t)BATCH * PRE_NMS * 32];

// ---------------- helpers ----------------
__device__ __forceinline__ uint32_t smem_u32(const void* p) {
    uint32_t a;
    asm("{ .reg .u64 t; cvta.to.shared.u64 t, %1; cvt.u32.u64 %0, t; }" : "=r"(a) : "l"(p));
    return a;
}
__device__ __forceinline__ void cp_async16(uint32_t dst, const void* src) {
    asm volatile("cp.async.cg.shared.global [%0], [%1], 16;" :: "r"(dst), "l"(src));
}
__device__ __forceinline__ void cp_commit() { asm volatile("cp.async.commit_group;" ::: "memory"); }
__device__ __forceinline__ void cp_wait2()  { asm volatile("cp.async.wait_group 2;" ::: "memory"); }
__device__ __forceinline__ void cp_wait1()  { asm volatile("cp.async.wait_group 1;" ::: "memory"); }
__device__ __forceinline__ void cp_wait0()  { asm volatile("cp.async.wait_group 0;" ::: "memory"); }

__device__ __forceinline__ void mma_bf16(float c[4], const uint32_t a[4], const uint32_t b[2]) {
    asm volatile("mma.sync.aligned.m16n8k16.row.col.f32.bf16.bf16.f32 "
        "{%0,%1,%2,%3}, {%4,%5,%6,%7}, {%8,%9}, {%0,%1,%2,%3};"
        : "+f"(c[0]), "+f"(c[1]), "+f"(c[2]), "+f"(c[3])
        : "r"(a[0]), "r"(a[1]), "r"(a[2]), "r"(a[3]), "r"(b[0]), "r"(b[1]));
}
__device__ __forceinline__ unsigned int rkey(float f) {
    unsigned u = __float_as_uint(f);
    u = (u & 0x80000000u) ? ~u : (u | 0x80000000u);
    return ~u;
}

// ---------------- im2col value (exact path; original K order c*27+off) ----------------
__device__ __forceinline__ float im2col_val(const float* __restrict__ bf, int b, int pos, int k) {
    int c = k / 27; int rem = k - c * 27;
    int kd = rem / 9, kh = (rem % 9) / 3, kw = rem % 3;
    int d = pos >> 10, h = (pos >> 5) & 31, w = pos & 31;
    int zd = d + kd - 1, zh = h + kh - 1, zw = w + kw - 1;
    if ((unsigned)zd < DD && (unsigned)zh < HH && (unsigned)zw < WW)
        return bf[(((size_t)(b * CIN + c) * DD + zd) * HH + zh) * WW + zw];
    return 0.f;
}

// ---------------- zero padded feature maps ----------------
__global__ void zero_fp_kernel() {
    size_t idx = (size_t)(blockIdx.x * 256 + threadIdx.x) * 8;
    if (idx < FPAD) {
        *(uint4*)(g_fp1 + idx) = make_uint4(0, 0, 0, 0);
        *(uint4*)(g_fp2 + idx) = make_uint4(0, 0, 0, 0);
    }
}

// ---------------- transpose + bf16 split ----------------
__global__ void tsplit_kernel(const float* __restrict__ bf) {
    __shared__ float tile[128][33];
    int blk = blockIdx.x;
    int b = blk >> 8;
    int d = (blk >> 5) & 7;
    int h = blk & 31;
    int t = threadIdx.x;

    int w = t & 31, cr = t >> 5;
#pragma unroll
    for (int i = 0; i < 16; i++) {
        int c = i * 8 + cr;
        tile[c][w] = bf[(((size_t)(b * CIN + c) * DD + d) << 10) + h * 32 + w];
    }
    __syncthreads();

    int c2 = t & 127, wr = t >> 7;
    size_t obase = ((((size_t)b * FPD + d + 1) * FPH + h + 1) * FPW + 1) * 128;
#pragma unroll
    for (int i = 0; i < 16; i++) {
        int w2 = i * 2 + wr;
        float v = tile[c2][w2];
        __nv_bfloat16 s1 = __float2bfloat16_rn(v);
        __nv_bfloat16 s2 = __float2bfloat16_rn(v - __bfloat162float(s1));
        g_fp1[obase + (size_t)w2 * 128 + c2] = s1;
        g_fp2[obase + (size_t)w2 * 128 + c2] = s2;
    }
}

// ---------------- weight reorder to k=(off, c), bf16 ----------------
__global__ void a_reord_kernel(const float* __restrict__ Wc) {
    int idx = blockIdx.x * 256 + threadIdx.x;
    if (idx >= COUT * KDIM) return;
    int m = idx / KDIM, k = idx - m * KDIM;
    int off = k >> 7, c = k & 127;
    g_ar[idx] = __float2bfloat16_rn(Wc[(size_t)m * KDIM + c * 27 + off]);
}

// ---------------- emu conv: implicit im2col, A bf16 x (B1+B2), swizzled smem ----------------
__device__ __forceinline__ void load_stage_emu(uint32_t sbase, int it, int m0,
                                               int bb, int dd, int h0, int tid) {
    int k0 = it * TILE_K;
    int off = k0 >> 7;
    int c0  = k0 & 127;
    int kd = off / 9; int r9 = off - kd * 9;
    int kh = r9 / 3;  int kw = r9 - kh * 3;

#pragma unroll
    for (int i = 0; i < 2; i++) {
        int cwp = i * 256 + tid;
        int row = cwp >> 2, quad = cwp & 3;
        uint32_t doff = (uint32_t)(row * 64 + ((quad ^ ((row >> 1) & 3)) << 4));
        cp_async16(sbase + doff, g_ar + (size_t)(m0 + row) * KDIM + k0 + quad * 8);
    }
#pragma unroll
    for (int i = 0; i < 4; i++) {
        int p = i >> 1;
        int cwp = (i & 1) * 256 + tid;
        int row = cwp >> 2, quad = cwp & 3;
        int h = h0 + (row >> 5);
        int w = row & 31;
        size_t base = ((((size_t)bb * FPD + dd + kd) * FPH + h + kh) * FPW + (w + kw)) * 128
                    + c0 + quad * 8;
        const __nv_bfloat16* src = (p == 0 ? g_fp1 : g_fp2) + base;
        uint32_t doff = (uint32_t)((p + 1) * (PLANE_W * 4) + row * 64
                                   + ((quad ^ ((row >> 1) & 3)) << 4));
        cp_async16(sbase + doff, src);
    }
    cp_commit();
}

__global__ __launch_bounds__(256, 3)
void conv_emu_kernel(const float* __restrict__ bias) {
    extern __shared__ __align__(16) uint32_t smem[];
    const int tid  = threadIdx.x;
    const int wid  = tid >> 5;
    const int lane = tid & 31;
    const int m0 = blockIdx.x * 128;
    const int n0 = blockIdx.y * 128;
    const int m_off = (wid >> 1) * 32;
    const int n_off = (wid & 1) * 64;
    const int qr = lane >> 2, qc = lane & 3;
    uint32_t sb = smem_u32(smem);

    const int bb = n0 >> 13;
    const int pos0 = n0 & (POS - 1);
    const int dd = pos0 >> 10;
    const int h0 = (pos0 >> 5) & 31;

    float acc[2][8][4];
#pragma unroll
    for (int i = 0; i < 2; i++)
#pragma unroll
        for (int j = 0; j < 8; j++)
#pragma unroll
            for (int t = 0; t < 4; t++) acc[i][j][t] = 0.f;

    load_stage_emu(sb, 0, m0, bb, dd, h0, tid);
    load_stage_emu(sb + STAGE_B, 1, m0, bb, dd, h0, tid);
    load_stage_emu(sb + 2 * STAGE_B, 2, m0, bb, dd, h0, tid);

    for (int it = 0; it < KITERS; it++) {
        if (it < KITERS - 2) cp_wait2();
        else if (it < KITERS - 1) cp_wait1();
        else cp_wait0();
        __syncthreads();

        const uint32_t* S = smem + (it % NSTG) * STAGE_W;
        const uint32_t* A1 = S;
        const uint32_t* B1 = S + PLANE_W;
        const uint32_t* B2 = S + 2 * PLANE_W;

#pragma unroll
        for (int q = 0; q < 2; q++) {
            uint32_t a1[2][4];
#pragma unroll
            for (int i = 0; i < 2; i++) {
                int r = m_off + i * 16 + qr;
                a1[i][0] = A1[SWIDX(r,     2*q,     qc)];
                a1[i][1] = A1[SWIDX(r + 8, 2*q,     qc)];
                a1[i][2] = A1[SWIDX(r,     2*q + 1, qc)];
                a1[i][3] = A1[SWIDX(r + 8, 2*q + 1, qc)];
            }
#pragma unroll
            for (int j = 0; j < 8; j++) {
                int n = n_off + j * 8 + qr;
                uint32_t b1[2] = { B1[SWIDX(n, 2*q, qc)], B1[SWIDX(n, 2*q + 1, qc)] };
                uint32_t b2[2] = { B2[SWIDX(n, 2*q, qc)], B2[SWIDX(n, 2*q + 1, qc)] };
#pragma unroll
                for (int i = 0; i < 2; i++) {
                    mma_bf16(acc[i][j], a1[i], b1);
                    mma_bf16(acc[i][j], a1[i], b2);
                }
            }
        }
        __syncthreads();
        if (it + NSTG < KITERS)
            load_stage_emu(sb + ((it + NSTG) % NSTG) * STAGE_B, it + NSTG, m0, bb, dd, h0, tid);
    }

#pragma unroll
    for (int i = 0; i < 2; i++) {
        int r0 = m0 + m_off + i * 16 + qr;
        float b0 = bias[r0], b1v = bias[r0 + 8];
#pragma unroll
        for (int j = 0; j < 8; j++) {
            int c0 = n0 + n_off + j * 8 + qc * 2;
            float2 v0, v1;
            v0.x = fmaxf(acc[i][j][0] + b0, 0.f);
            v0.y = fmaxf(acc[i][j][1] + b0, 0.f);
            v1.x = fmaxf(acc[i][j][2] + b1v, 0.f);
            v1.y = fmaxf(acc[i][j][3] + b1v, 0.f);
            *(float2*)(g_xe + (size_t)r0 * NCOL + c0) = v0;
            *(float2*)(g_xe + (size_t)(r0 + 8) * NCOL + c0) = v1;
        }
    }
}

// ---------------- emu heads: 18 cls rows, dedicated kernel ----------------
__global__ __launch_bounds__(128)
void head18_kernel() {
    __shared__ float w[CLSROWS * 512];
    int t = threadIdx.x;
    for (int i = t; i < CLSROWS * 512; i += 128) w[i] = g_wh[i];
    __syncthreads();
    int n = blockIdx.x * 128 + t;
    float acc[CLSROWS];
#pragma unroll
    for (int r = 0; r < CLSROWS; r++) acc[r] = g_bh[r];
    for (int k = 0; k < 512; k++) {
        float xv = g_xe[(size_t)k * NCOL + n];
#pragma unroll
        for (int r = 0; r < CLSROWS; r++) acc[r] = fmaf(w[r * 512 + k], xv, acc[r]);
    }
#pragma unroll
    for (int r = 0; r < CLSROWS; r++) g_h[(size_t)r * NCOL + n] = acc[r];
}

// ---------------- exact GEMM, 32m x 64n tiles (bit-identical k-ascending fmaf chains) ----------------
__global__ __launch_bounds__(128)
void exact32x64(const float* __restrict__ A, const float* __restrict__ B,
                float* __restrict__ C, const float* __restrict__ bias,
                int M, int N, int K, int doRelu, const int* __restrict__ nlim) {
    if (blockIdx.x * 64 >= *nlim) return;
    __shared__ float As[2][8][32];
    __shared__ float Bs[2][8][64];
    const int tid = threadIdx.x;
    const int m0 = blockIdx.y * 32;
    const int n0 = blockIdx.x * 64;
    const int mg = tid >> 4, ng = tid & 15;
    const int am = tid & 31, akq = (tid >> 5) * 4;
    const int bk = tid >> 4, bn4 = (tid & 15) * 4;

    float acc[4][4];
#pragma unroll
    for (int i = 0; i < 4; i++)
#pragma unroll
        for (int j = 0; j < 4; j++) acc[i][j] = 0.f;

    float4 av = make_float4(0.f, 0.f, 0.f, 0.f), bv;
    {
        if (tid < 64) {
            int gm = m0 + am;
            if (gm < M) av = *(const float4*)(A + (size_t)gm * K + akq);
        }
        bv = *(const float4*)(B + (size_t)bk * N + n0 + bn4);
        if (tid < 64) {
            As[0][akq + 0][am] = av.x; As[0][akq + 1][am] = av.y;
            As[0][akq + 2][am] = av.z; As[0][akq + 3][am] = av.w;
        }
        *(float4*)&Bs[0][bk][bn4] = bv;
    }
    __syncthreads();

    int cur = 0;
    for (int kt = 8; kt < K; kt += 8) {
        av = make_float4(0.f, 0.f, 0.f, 0.f);
        if (tid < 64) {
            int gm = m0 + am;
            if (gm < M) av = *(const float4*)(A + (size_t)gm * K + kt + akq);
        }
        bv = *(const float4*)(B + (size_t)(kt + bk) * N + n0 + bn4);

#pragma unroll
        for (int kk = 0; kk < 8; kk++) {
            float4 a = *(const float4*)&As[cur][kk][mg * 4];
            float4 b = *(const float4*)&Bs[cur][kk][ng * 4];
            acc[0][0] = fmaf(a.x, b.x, acc[0][0]); acc[0][1] = fmaf(a.x, b.y, acc[0][1]);
            acc[0][2] = fmaf(a.x, b.z, acc[0][2]); acc[0][3] = fmaf(a.x, b.w, acc[0][3]);
            acc[1][0] = fmaf(a.y, b.x, acc[1][0]); acc[1][1] = fmaf(a.y, b.y, acc[1][1]);
            acc[1][2] = fmaf(a.y, b.z, acc[1][2]); acc[1][3] = fmaf(a.y, b.w, acc[1][3]);
            acc[2][0] = fmaf(a.z, b.x, acc[2][0]); acc[2][1] = fmaf(a.z, b.y, acc[2][1]);
            acc[2][2] = fmaf(a.z, b.z, acc[2][2]); acc[2][3] = fmaf(a.z, b.w, acc[2][3]);
            acc[3][0] = fmaf(a.w, b.x, acc[3][0]); acc[3][1] = fmaf(a.w, b.y, acc[3][1]);
            acc[3][2] = fmaf(a.w, b.z, acc[3][2]); acc[3][3] = fmaf(a.w, b.w, acc[3][3]);
        }
        int nxt = cur ^ 1;
        if (tid < 64) {
            As[nxt][akq + 0][am] = av.x; As[nxt][akq + 1][am] = av.y;
            As[nxt][akq + 2][am] = av.z; As[nxt][akq + 3][am] = av.w;
        }
        *(float4*)&Bs[nxt][bk][bn4] = bv;
        __syncthreads();
        cur = nxt;
    }
#pragma unroll
    for (int kk = 0; kk < 8; kk++) {
        float4 a = *(const float4*)&As[cur][kk][mg * 4];
        float4 b = *(const float4*)&Bs[cur][kk][ng * 4];
        acc[0][0] = fmaf(a.x, b.x, acc[0][0]); acc[0][1] = fmaf(a.x, b.y, acc[0][1]);
        acc[0][2] = fmaf(a.x, b.z, acc[0][2]); acc[0][3] = fmaf(a.x, b.w, acc[0][3]);
        acc[1][0] = fmaf(a.y, b.x, acc[1][0]); acc[1][1] = fmaf(a.y, b.y, acc[1][1]);
        acc[1][2] = fmaf(a.y, b.z, acc[1][2]); acc[1][3] = fmaf(a.y, b.w, acc[1][3]);
        acc[2][0] = fmaf(a.z, b.x, acc[2][0]); acc[2][1] = fmaf(a.z, b.y, acc[2][1]);
        acc[2][2] = fmaf(a.z, b.z, acc[2][2]); acc[2][3] = fmaf(a.z, b.w, acc[2][3]);
        acc[3][0] = fmaf(a.w, b.x, acc[3][0]); acc[3][1] = fmaf(a.w, b.y, acc[3][1]);
        acc[3][2] = fmaf(a.w, b.z, acc[3][2]); acc[3][3] = fmaf(a.w, b.w, acc[3][3]);
    }

#pragma unroll
    for (int i = 0; i < 4; i++) {
        int gm = m0 + mg * 4 + i;
        if (gm >= M) continue;
        float bb = bias[gm];
        float4 v;
        v.x = acc[i][0] + bb; v.y = acc[i][1] + bb;
        v.z = acc[i][2] + bb; v.w = acc[i][3] + bb;
        if (doRelu) {
            v.x = fmaxf(v.x, 0.f); v.y = fmaxf(v.y, 0.f);
            v.z = fmaxf(v.z, 0.f); v.w = fmaxf(v.w, 0.f);
        }
        *(float4*)(C + (size_t)gm * N + n0 + ng * 4) = v;
    }
}

// ---------------- pack head weights ----------------
__global__ void pack_head(const float* __restrict__ Wc, const float* __restrict__ bc,
                          const float* __restrict__ Wb, const float* __restrict__ bb) {
    int idx = blockIdx.x * 256 + threadIdx.x;
    if (idx < HROWS * 512) {
        int row = idx / 512, col = idx % 512;
        g_wh[idx] = (row < 18) ? Wc[row * 512 + col] : Wb[(row - 18) * 512 + col];
    }
    if (idx < HROWS) g_bh[idx] = (idx < 18) ? bc[idx] : bb[idx - 18];
}

// ---------------- emu scores + clear ----------------
__global__ void escore_kernel() {
    int idx = blockIdx.x * 256 + threadIdx.x;
    if (idx < BATCH * POS) g_pflag[idx] = 0;
    if (idx >= BATCH * NPROP) return;
    g_scores[idx] = 0.f;
    int b = idx / NPROP;
    int i = idx - b * NPROP;
    int pos = i / NANCH;
    int a = i - pos * NANCH;
    int n = b * POS + pos;
    float l0 = g_h[(size_t)a * NCOL + n];
    float l1 = g_h[(size_t)(NANCH + a) * NCOL + n];
    float mx = fmaxf(l0, l1);
    float e0 = expf(l0 - mx), e1 = expf(l1 - mx);
    g_escore[idx] = e1 / (e0 + e1);
}

// ---------------- emu cutoff (2048th) ----------------
__global__ __launch_bounds__(1024)
void cutoff_kernel() {
    const int b = blockIdx.x;
    const int tid = threadIdx.x;
    const float* sc = g_escore + (size_t)b * NPROP;
    __shared__ unsigned sh_hist[256];
    __shared__ unsigned sh_prefix;
    __shared__ int sh_need;
    if (tid == 0) { sh_prefix = 0; sh_need = PRE_NMS; }
    __syncthreads();
    for (int p = 3; p >= 0; p--) {
        for (int v = tid; v < 256; v += 1024) sh_hist[v] = 0;
        __syncthreads();
        unsigned pref = sh_prefix;
        unsigned pm = (p == 3) ? 0u : (0xFFFFFFFFu << ((p + 1) * 8));
        for (int i = tid; i < NPROP; i += 1024) {
            unsigned rk = rkey(sc[i]);
            if ((rk & pm) == pref) atomicAdd(&sh_hist[(rk >> (p * 8)) & 255], 1u);
        }
        __syncthreads();
        if (tid == 0) {
            int need = sh_need;
            unsigned acc = 0;
            for (int v = 0; v < 256; v++) {
                unsigned c = sh_hist[v];
                if (need <= (int)(acc + c)) {
                    sh_prefix = pref | ((unsigned)v << (p * 8));
                    sh_need = need - (int)acc;
                    break;
                }
                acc += c;
            }
        }
        __syncthreads();
    }
    if (tid == 0) {
        unsigned m = ~sh_prefix;
        float cf = __uint_as_float(m & 0x7FFFFFFFu);
        g_thr[b] = cf - MARGIN;
    }
}

// ---------------- candidate flags ----------------
__global__ void flag_kernel() {
    int idx = blockIdx.x * 256 + threadIdx.x;
    if (idx >= BATCH * NPROP) return;
    int b = idx / NPROP;
    if (g_escore[idx] >= g_thr[b]) {
        int pos = (idx - b * NPROP) / NANCH;
        g_pflag[b * POS + pos] = 1;
    }
}

// ---------------- compaction ----------------
__global__ __launch_bounds__(1024)
void compact_kernel() {
    __shared__ int warp_sums[32];
    __shared__ int base_off;
    int tid = threadIdx.x;
    int lane = tid & 31, wrp = tid >> 5;
    if (tid == 0) base_off = 0;
    __syncthreads();
    for (int b = 0; b < BATCH; b++) {
        int cnt = 0;
        int mypos[8];
#pragma unroll
        for (int u = 0; u < 8; u++) {
            int pos = tid * 8 + u;
            if (g_pflag[b * POS + pos]) mypos[cnt++] = pos;
        }
        int v = cnt;
#pragma unroll
        for (int o = 1; o < 32; o <<= 1) {
            int t = __shfl_up_sync(0xffffffffu, v, o);
            if (lane >= o) v += t;
        }
        if (lane == 31) warp_sums[wrp] = v;
        __syncthreads();
        if (wrp == 0) {
            int wv = warp_sums[lane];
#pragma unroll
            for (int o = 1; o < 32; o <<= 1) {
                int t = __shfl_up_sync(0xffffffffu, wv, o);
                if (lane >= o) wv += t;
            }
            warp_sums[lane] = wv;
        }
        __syncthreads();
        int excl = v - cnt + (wrp ? warp_sums[wrp - 1] : 0);
        int bo = base_off;
        for (int u = 0; u < cnt; u++) {
            int slot = bo + excl + u;
            if (slot < CCAP) g_plist[slot] = b * POS + mypos[u];
        }
        __syncthreads();
        if (tid == 0) {
            int tot = warp_sums[31];
            int nb = base_off + tot; if (nb > CCAP) nb = CCAP;
            if (b == 0) g_nc[0] = nb;
            base_off = nb;
            if (b == BATCH - 1) {
                g_nc[1] = base_off;
                g_nc[2] = (base_off + 63) & ~63;
            }
        }
        __syncthreads();
    }
}

// ---------------- gather (coalesced writes) ----------------
__global__ void gather_kernel(const float* __restrict__ bf) {
    int j0 = blockIdx.x * 32;
    if (j0 >= g_nc[1]) return;
    int jl = threadIdx.x & 31;
    int kl = threadIdx.x >> 5;
    int j = j0 + jl;
    int n = g_plist[j];
    int b = n >> 13, pos = n & (POS - 1);
#pragma unroll
    for (int kk = 0; kk < 16; kk++) {
        int k = blockIdx.y * 128 + kl * 16 + kk;
        g_colc[(size_t)k * CW + j] = im2col_val(bf, b, pos, k);
    }
}

// ---------------- exact decode for candidates ----------------
__global__ void decode_cand_kernel(const float* __restrict__ im_info) {
    int idx = blockIdx.x * 256 + threadIdx.x;
    int cidx = idx / NANCH;
    if (cidx >= g_nc[1]) return;
    int a = idx - cidx * NANCH;
    int n = g_plist[cidx];
    int b = n >> 13, pos = n & (POS - 1);
    int i = pos * NANCH + a;

    float l0 = g_hc[(size_t)a * CW + cidx];
    float l1 = g_hc[(size_t)(NANCH + a) * CW + cidx];
    float mx = fmaxf(l0, l1);
    float e0 = expf(l0 - mx), e1 = expf(l1 - mx);
    g_scores[(size_t)b * NPROP + i] = e1 / (e0 + e1);

    const float* hd = g_hc + (size_t)(18 + a * 6) * CW + cidx;
    float dx = hd[0 * (size_t)CW], dy = hd[1 * (size_t)CW], dz = hd[2 * (size_t)CW];
    float dw = hd[3 * (size_t)CW], dh = hd[4 * (size_t)CW], dd = hd[5 * (size_t)CW];

    int wp = pos & 31, hp = (pos >> 5) & 31, dp = pos >> 10;
    float s = 4.f * (float)(1 << (a % 3));
    float r = 0.5f * (float)(1 << (a / 3));
    float wsz = 8.f * s;
    float dsz = 8.f * s * r;
    const float ctr = 3.5f;
    float sx = wp * 8.f, sy = hp * 8.f, sz = dp * 8.f;

    float x1 = sx + ctr - 0.5f * (wsz - 1.f), x2 = sx + ctr + 0.5f * (wsz - 1.f);
    float y1 = sy + ctr - 0.5f * (wsz - 1.f), y2 = sy + ctr + 0.5f * (wsz - 1.f);
    float z1 = sz + ctr - 0.5f * (dsz - 1.f), z2 = sz + ctr + 0.5f * (dsz - 1.f);

    float aw = x2 - x1 + 1.f, ah = y2 - y1 + 1.f, ad = z2 - z1 + 1.f;
    float cx = x1 + 0.5f * aw, cy = y1 + 0.5f * ah, cz = z1 + 0.5f * ad;

    float pcx = dx * aw + cx, pcy = dy * ah + cy, pcz = dz * ad + cz;
    float pw = expf(dw) * aw, ph = expf(dh) * ah, pd = expf(dd) * ad;

    float ox1 = pcx - 0.5f * pw, oy1 = pcy - 0.5f * ph, oz1 = pcz - 0.5f * pd;
    float ox2 = pcx + 0.5f * pw, oy2 = pcy + 0.5f * ph, oz2 = pcz + 0.5f * pd;

    float hix = im_info[b * 3 + 2] - 1.f;
    float hiy = im_info[b * 3 + 1] - 1.f;
    float hiz = im_info[b * 3 + 0] - 1.f;
    ox1 = fminf(fmaxf(ox1, 0.f), hix); ox2 = fminf(fmaxf(ox2, 0.f), hix);
    oy1 = fminf(fmaxf(oy1, 0.f), hiy); oy2 = fminf(fmaxf(oy2, 0.f), hiy);
    oz1 = fminf(fmaxf(oz1, 0.f), hiz); oz2 = fminf(fmaxf(oz2, 0.f), hiz);

    float* ob = g_boxes + ((size_t)b * NPROP + i) * 6;
    ob[0] = ox1; ob[1] = oy1; ob[2] = oz1; ob[3] = ox2; ob[4] = oy2; ob[5] = oz2;
}

// ---------------- top-2048 select (exact jax top_k order) ----------------
__global__ __launch_bounds__(1024)
void select_topk_kernel() {
    const int b = blockIdx.x;
    const int tid = threadIdx.x;
    const float* sc = g_scores + (size_t)b * NPROP;

    __shared__ unsigned sh_hist[256];
    __shared__ unsigned sh_prefix;
    __shared__ int sh_need;
    __shared__ int sh_cnt;
    __shared__ unsigned long long s[4096];

    if (tid == 0) { sh_prefix = 0; sh_need = PRE_NMS; }
    __syncthreads();

    for (int p = 3; p >= 0; p--) {
        for (int v = tid; v < 256; v += 1024) sh_hist[v] = 0;
        __syncthreads();
        unsigned pref = sh_prefix;
        unsigned pm = (p == 3) ? 0u : (0xFFFFFFFFu << ((p + 1) * 8));
        for (int i = tid; i < NPROP; i += 1024) {
            unsigned rk = rkey(sc[i]);
            if ((rk & pm) == pref) atomicAdd(&sh_hist[(rk >> (p * 8)) & 255], 1u);
        }
        __syncthreads();
        if (tid == 0) {
            int need = sh_need;
            unsigned acc = 0;
            for (int v = 0; v < 256; v++) {
                unsigned c = sh_hist[v];
                if (need <= (int)(acc + c)) {
                    sh_prefix = pref | ((unsigned)v << (p * 8));
                    sh_need = need - (int)acc;
                    break;
                }
                acc += c;
            }
        }
        __syncthreads();
    }
    unsigned cutoff = sh_prefix;
    if (tid == 0) sh_cnt = 0;
    __syncthreads();

    for (int i = tid; i < NPROP; i += 1024) {
        unsigned rk = rkey(sc[i]);
        if (rk <= cutoff) {
            int posn = atomicAdd(&sh_cnt, 1);
            if (posn < 4096)
                g_cand[b][posn] = ((unsigned long long)rk << 32) | (unsigned)i;
        }
    }
    __syncthreads();
    int total = sh_cnt; if (total > 4096) total = 4096;
    for (int i = tid; i < 4096; i += 1024)
        s[i] = (i < total) ? g_cand[b][i] : 0xFFFFFFFFFFFFFFFFull;
    __syncthreads();

    for (int k = 2; k <= 4096; k <<= 1) {
        for (int j = k >> 1; j > 0; j >>= 1) {
            for (int i = tid; i < 4096; i += 1024) {
                int l = i ^ j;
                if (l > i) {
                    unsigned long long a = s[i], c = s[l];
                    bool sw = ((i & k) == 0) ? (a > c) : (a < c);
                    if (sw) { s[i] = c; s[l] = a; }
                }
            }
            __syncthreads();
        }
    }

    for (int r2 = tid; r2 < PRE_NMS; r2 += 1024) {
        unsigned idx = (unsigned)(s[r2] & 0xFFFFFFFFull);
        const float* src = g_boxes + ((size_t)b * NPROP + idx) * 6;
        float* dst = g_sboxes + ((size_t)b * PRE_NMS + r2) * 6;
#pragma unroll
        for (int c = 0; c < 6; c++) dst[c] = src[c];
    }
}

// ---------------- NMS bitmask ----------------
__global__ void nms_mask_kernel() {
    int b = blockIdx.z, jb = blockIdx.x, ib = blockIdx.y, t = threadIdx.x;
    __shared__ float cb[64][6];
    const float* sb = g_sboxes + (size_t)b * PRE_NMS * 6;
    {
        const float* p = sb + (size_t)(jb * 64 + t) * 6;
#pragma unroll
        for (int c = 0; c < 6; c++) cb[t][c] = p[c];
    }
    __syncthreads();

    int i = ib * 64 + t;
    const float* p = sb + (size_t)i * 6;
    float x1 = p[0], y1 = p[1], z1 = p[2], x2 = p[3], y2 = p[4], z2 = p[5];
    float vi = (x2 - x1 + 1.f) * (y2 - y1 + 1.f) * (z2 - z1 + 1.f);
    unsigned long long bits = 0ull;
#pragma unroll 4
    for (int jj = 0; jj < 64; jj++) {
        float ix = fmaxf(fminf(x2, cb[jj][3]) - fmaxf(x1, cb[jj][0]) + 1.f, 0.f);
        float iy = fmaxf(fminf(y2, cb[jj][4]) - fmaxf(y1, cb[jj][1]) + 1.f, 0.f);
        float iz = fmaxf(fminf(z2, cb[jj][5]) - fmaxf(z1, cb[jj][2]) + 1.f, 0.f);
        float inter = ix * iy * iz;
        float vj = (cb[jj][3] - cb[jj][0] + 1.f) * (cb[jj][4] - cb[jj][1] + 1.f)
                 * (cb[jj][5] - cb[jj][2] + 1.f);
        float iou = inter / (vi + vj - inter);
        if (iou > NMS_TH) bits |= (1ull << jj);
    }
    g_mask[((size_t)b * PRE_NMS + i) * 32 + jb] = bits;
}

// ---------------- sequential keep-scan + output (16-deep prefetch ring) ----------------
__global__ void nms_scan_kernel(float* __restrict__ out) {
    int b = blockIdx.x;
    int lane = threadIdx.x;
    __shared__ unsigned short keep[POST_NMS];
    unsigned long long rem = 0ull;
    int nk = 0;
    const unsigned long long* mb = g_mask + (size_t)b * PRE_NMS * 32;

    unsigned long long pf[16];
#pragma unroll
    for (int u = 0; u < 16; u++) pf[u] = mb[(size_t)u * 32 + lane];

    for (int base = 0; base < PRE_NMS; base += 16) {
#pragma unroll
        for (int u = 0; u < 16; u++) {
            int i = base + u;
            unsigned long long w = __shfl_sync(0xffffffffu, rem, i >> 6);
            unsigned long long m = pf[u];
            int nx = i + 16;
            if (nx < PRE_NMS) pf[u] = mb[(size_t)nx * 32 + lane];
            if (!((w >> (i & 63)) & 1ull)) {
                if (lane == 0 && nk < POST_NMS) keep[nk] = (unsigned short)i;
                nk++;
                rem |= m;
            }
        }
    }
    __syncwarp();
    for (int r = lane; r < POST_NMS; r += 32) {
        float* o = out + ((size_t)b * POST_NMS + r) * 7;
        o[0] = (float)b;
        if (r < nk) {
            int i = keep[r];
            const float* bx = g_sboxes + ((size_t)b * PRE_NMS + i) * 6;
#pragma unroll
            for (int c = 0; c < 6; c++) o[1 + c] = bx[c];
        } else {
#pragma unroll
            for (int c = 0; c < 6; c++) o[1 + c] = 0.f;
        }
    }
}

// ---------------- launch ----------------
extern "C" void kernel_launch(void* const* d_in, const int* in_sizes, int n_in,
                              void* d_out, int out_size) {
    const float* base_feat = (const float*)d_in[0];
    const float* im_info   = (const float*)d_in[1];
    const float* W_conv    = (const float*)d_in[4];
    const float* b_conv    = (const float*)d_in[5];
    const float* W_cls     = (const float*)d_in[6];
    const float* b_cls     = (const float*)d_in[7];
    const float* W_bbox    = (const float*)d_in[8];
    const float* b_bbox    = (const float*)d_in[9];
    float* out = (float*)d_out;

    float *p_wh, *p_bh, *p_colc, *p_xc, *p_hc;
    int* p_nc;
    cudaGetSymbolAddress((void**)&p_wh,   g_wh);
    cudaGetSymbolAddress((void**)&p_bh,   g_bh);
    cudaGetSymbolAddress((void**)&p_colc, g_colc);
    cudaGetSymbolAddress((void**)&p_xc,   g_xc);
    cudaGetSymbolAddress((void**)&p_hc,   g_hc);
    cudaGetSymbolAddress((void**)&p_nc,   g_nc);

    cudaFuncSetAttribute(conv_emu_kernel, cudaFuncAttributeMaxDynamicSharedMemorySize, SMEM_EMU);

    zero_fp_kernel<<<(int)((FPAD / 8 + 255) / 256), 256>>>();
    tsplit_kernel<<<BATCH * DD * HH, 256>>>(base_feat);
    a_reord_kernel<<<(COUT * KDIM + 255) / 256, 256>>>(W_conv);
    {   // emu conv (implicit im2col, swizzled smem, 3 CTAs/SM)
        dim3 grid(COUT / 128, NCOL / 128);
        conv_emu_kernel<<<grid, 256, SMEM_EMU>>>(b_conv);
    }
    pack_head<<<(HROWS * 512 + 255) / 256, 256>>>(W_cls, b_cls, W_bbox, b_bbox);
    head18_kernel<<<NCOL / 128, 128>>>();
    escore_kernel<<<(BATCH * NPROP + 255) / 256, 256>>>();
    cutoff_kernel<<<BATCH, 1024>>>();
    flag_kernel<<<(BATCH * NPROP + 255) / 256, 256>>>();
    compact_kernel<<<1, 1024>>>();
    {
        dim3 grid(CCAP / 32, 27);
        gather_kernel<<<grid, 256>>>(base_feat);
    }
    {   // exact conv on compacted columns (32x64 tiles, R1-identical numerics)
        dim3 grid(CW / 64, COUT / 32);
        exact32x64<<<grid, 128>>>(W_conv, p_colc, p_xc, b_conv, COUT, CW, KDIM, 1, p_nc + 2);
    }
    {   // exact heads on compacted columns
        dim3 grid(CW / 64, (HROWS + 31) / 32);
        exact32x64<<<grid, 128>>>(p_wh, p_xc, p_hc, p_bh, HROWS, CW, 512, 0, p_nc + 2);
    }
    decode_cand_kernel<<<(CCAP * NANCH + 255) / 256, 256>>>(im_info);
    select_topk_kernel<<<BATCH, 1024>>>();
    {
        dim3 grid(PRE_NMS / 64, PRE_NMS / 64, BATCH);
        nms_mask_kernel<<<grid, 64>>>();
    }
    nms_scan_kernel<<<BATCH, 32>>>(out);
}

// round 14
// speedup vs baseline: 1.0579x; 1.0579x over previous
#include <cuda_runtime.h>
#include <cuda_bf16.h>
#include <math.h>
#include <stdint.h>

// ---------------- problem constants ----------------
#define BATCH   2
#define CIN     128
#define COUT    512
#define DD      8
#define HH      32
#define WW      32
#define POS     (DD*HH*WW)          // 8192
#define NCOL    (BATCH*POS)         // 16384
#define KDIM    (CIN*27)            // 3456
#define NANCH   9
#define NPROP   (POS*NANCH)         // 73728 per batch
#define PRE_NMS 2048
#define POST_NMS 300
#define NMS_TH  0.7f
#define HROWS   72
#define CLSROWS 18
#define MARGIN  1e-3f
#define CCAP    8192
#define CW      8192

// emu conv tiling (A bf16 x B bf16x2), K reordered as (off, c)
#define TILE_K    32
#define KITERS    (KDIM/TILE_K)     // 108
#define PLANE_W   (128*20)
#define STAGE_W   (3*PLANE_W)       // A, B1, B2
#define STAGE_B   (STAGE_W*4)       // 30720 bytes
#define NSTG      3
#define SMEM_EMU  (NSTG*STAGE_B)    // 92160

// padded transposed feature map: [B][D+2][H+2][W+2][C]
#define FPD     (DD+2)
#define FPH     (HH+2)
#define FPW     (WW+2)
#define FPAD    ((size_t)BATCH*FPD*FPH*FPW*CIN)

// ---------------- static scratch ----------------
__device__ __align__(128) __nv_bfloat16 g_fp1[FPAD];
__device__ __align__(128) __nv_bfloat16 g_fp2[FPAD];
__device__ __align__(128) __nv_bfloat16 g_ar [(size_t)COUT * KDIM];
__device__ float g_xe  [(size_t)COUT * NCOL];
__device__ float g_h   [(size_t)CLSROWS * NCOL];
__device__ float g_colc[(size_t)KDIM * CW];
__device__ float g_xc  [(size_t)COUT * CW];
__device__ float g_hc  [(size_t)HROWS * CW];
__device__ float g_wh  [HROWS * 512];
__device__ float g_bh  [HROWS];
__device__ float g_escore[BATCH * NPROP];
__device__ float g_thr[BATCH];
__device__ int   g_pflag[BATCH * POS];
__device__ int   g_plist[CCAP];
__device__ int   g_nc[4];
__device__ float g_scores[BATCH * NPROP];
__device__ float g_boxes [(size_t)BATCH * NPROP * 6];
__device__ unsigned long long g_cand[BATCH][4096];
__device__ float g_sboxes[(size_t)BATCH * PRE_NMS * 6];
__device__ unsigned long long g_mask[(size_t)BATCH * PRE_NMS * 32];

// ---------------- helpers ----------------
__device__ __forceinline__ uint32_t smem_u32(const void* p) {
    uint32_t a;
    asm("{ .reg .u64 t; cvta.to.shared.u64 t, %1; cvt.u32.u64 %0, t; }" : "=r"(a) : "l"(p));
    return a;
}
__device__ __forceinline__ void cp_async16(uint32_t dst, const void* src) {
    asm volatile("cp.async.cg.shared.global [%0], [%1], 16;" :: "r"(dst), "l"(src));
}
__device__ __forceinline__ void cp_commit() { asm volatile("cp.async.commit_group;" ::: "memory"); }
__device__ __forceinline__ void cp_wait2()  { asm volatile("cp.async.wait_group 2;" ::: "memory"); }
__device__ __forceinline__ void cp_wait1()  { asm volatile("cp.async.wait_group 1;" ::: "memory"); }
__device__ __forceinline__ void cp_wait0()  { asm volatile("cp.async.wait_group 0;" ::: "memory"); }

__device__ __forceinline__ void mma_bf16(float c[4], const uint32_t a[4], const uint32_t b[2]) {
    asm volatile("mma.sync.aligned.m16n8k16.row.col.f32.bf16.bf16.f32 "
        "{%0,%1,%2,%3}, {%4,%5,%6,%7}, {%8,%9}, {%0,%1,%2,%3};"
        : "+f"(c[0]), "+f"(c[1]), "+f"(c[2]), "+f"(c[3])
        : "r"(a[0]), "r"(a[1]), "r"(a[2]), "r"(a[3]), "r"(b[0]), "r"(b[1]));
}
__device__ __forceinline__ unsigned int rkey(float f) {
    unsigned u = __float_as_uint(f);
    u = (u & 0x80000000u) ? ~u : (u | 0x80000000u);
    return ~u;
}

// ---------------- im2col value (exact path; original K order c*27+off) ----------------
__device__ __forceinline__ float im2col_val(const float* __restrict__ bf, int b, int pos, int k) {
    int c = k / 27; int rem = k - c * 27;
    int kd = rem / 9, kh = (rem % 9) / 3, kw = rem % 3;
    int d = pos >> 10, h = (pos >> 5) & 31, w = pos & 31;
    int zd = d + kd - 1, zh = h + kh - 1, zw = w + kw - 1;
    if ((unsigned)zd < DD && (unsigned)zh < HH && (unsigned)zw < WW)
        return bf[(((size_t)(b * CIN + c) * DD + zd) * HH + zh) * WW + zw];
    return 0.f;
}

// ---------------- zero padded feature maps ----------------
__global__ void zero_fp_kernel() {
    size_t idx = (size_t)(blockIdx.x * 256 + threadIdx.x) * 8;
    if (idx < FPAD) {
        *(uint4*)(g_fp1 + idx) = make_uint4(0, 0, 0, 0);
        *(uint4*)(g_fp2 + idx) = make_uint4(0, 0, 0, 0);
    }
}

// ---------------- transpose + bf16 split ----------------
__global__ void tsplit_kernel(const float* __restrict__ bf) {
    __shared__ float tile[128][33];
    int blk = blockIdx.x;
    int b = blk >> 8;
    int d = (blk >> 5) & 7;
    int h = blk & 31;
    int t = threadIdx.x;

    int w = t & 31, cr = t >> 5;
#pragma unroll
    for (int i = 0; i < 16; i++) {
        int c = i * 8 + cr;
        tile[c][w] = bf[(((size_t)(b * CIN + c) * DD + d) << 10) + h * 32 + w];
    }
    __syncthreads();

    int c2 = t & 127, wr = t >> 7;
    size_t obase = ((((size_t)b * FPD + d + 1) * FPH + h + 1) * FPW + 1) * 128;
#pragma unroll
    for (int i = 0; i < 16; i++) {
        int w2 = i * 2 + wr;
        float v = tile[c2][w2];
        __nv_bfloat16 s1 = __float2bfloat16_rn(v);
        __nv_bfloat16 s2 = __float2bfloat16_rn(v - __bfloat162float(s1));
        g_fp1[obase + (size_t)w2 * 128 + c2] = s1;
        g_fp2[obase + (size_t)w2 * 128 + c2] = s2;
    }
}

// ---------------- weight reorder to k=(off, c), bf16 ----------------
__global__ void a_reord_kernel(const float* __restrict__ Wc) {
    int idx = blockIdx.x * 256 + threadIdx.x;
    if (idx >= COUT * KDIM) return;
    int m = idx / KDIM, k = idx - m * KDIM;
    int off = k >> 7, c = k & 127;
    g_ar[idx] = __float2bfloat16_rn(Wc[(size_t)m * KDIM + c * 27 + off]);
}

// ---------------- emu conv: implicit im2col, A bf16 x (B1+B2) ----------------
__device__ __forceinline__ void load_stage_emu(uint32_t sbase, int it, int m0,
                                               int bb, int dd, int h0, int tid) {
    int k0 = it * TILE_K;
    int off = k0 >> 7;
    int c0  = k0 & 127;
    int kd = off / 9; int r9 = off - kd * 9;
    int kh = r9 / 3;  int kw = r9 - kh * 3;

#pragma unroll
    for (int i = 0; i < 2; i++) {
        int cwp = i * 256 + tid;
        int row = cwp >> 2, quad = cwp & 3;
        uint32_t doff = (uint32_t)(row * 80 + quad * 16);
        cp_async16(sbase + doff, g_ar + (size_t)(m0 + row) * KDIM + k0 + quad * 8);
    }
#pragma unroll
    for (int i = 0; i < 4; i++) {
        int p = i >> 1;
        int cwp = (i & 1) * 256 + tid;
        int row = cwp >> 2, quad = cwp & 3;
        int h = h0 + (row >> 5);
        int w = row & 31;
        size_t base = ((((size_t)bb * FPD + dd + kd) * FPH + h + kh) * FPW + (w + kw)) * 128
                    + c0 + quad * 8;
        const __nv_bfloat16* src = (p == 0 ? g_fp1 : g_fp2) + base;
        uint32_t doff = (uint32_t)((p + 1) * (PLANE_W * 4) + row * 80 + quad * 16);
        cp_async16(sbase + doff, src);
    }
    cp_commit();
}

__global__ __launch_bounds__(256)
void conv_emu_kernel(const float* __restrict__ bias) {
    extern __shared__ __align__(16) uint32_t smem[];
    const int tid  = threadIdx.x;
    const int wid  = tid >> 5;
    const int lane = tid & 31;
    const int m0 = blockIdx.x * 128;
    const int n0 = blockIdx.y * 128;
    const int m_off = (wid >> 1) * 32;
    const int n_off = (wid & 1) * 64;
    const int qr = lane >> 2, qc = lane & 3;
    uint32_t sb = smem_u32(smem);

    const int bb = n0 >> 13;
    const int pos0 = n0 & (POS - 1);
    const int dd = pos0 >> 10;
    const int h0 = (pos0 >> 5) & 31;

    float acc[2][8][4];
#pragma unroll
    for (int i = 0; i < 2; i++)
#pragma unroll
        for (int j = 0; j < 8; j++)
#pragma unroll
            for (int t = 0; t < 4; t++) acc[i][j][t] = 0.f;

    load_stage_emu(sb, 0, m0, bb, dd, h0, tid);
    load_stage_emu(sb + STAGE_B, 1, m0, bb, dd, h0, tid);
    load_stage_emu(sb + 2 * STAGE_B, 2, m0, bb, dd, h0, tid);

    for (int it = 0; it < KITERS; it++) {
        if (it < KITERS - 2) cp_wait2();
        else if (it < KITERS - 1) cp_wait1();
        else cp_wait0();
        __syncthreads();

        const uint32_t* S = smem + (it % NSTG) * STAGE_W;
        const uint32_t* A1 = S;
        const uint32_t* B1 = S + PLANE_W;
        const uint32_t* B2 = S + 2 * PLANE_W;

#pragma unroll
        for (int q = 0; q < 2; q++) {
            int w0 = q * 8 + qc;
            uint32_t a1[2][4];
#pragma unroll
            for (int i = 0; i < 2; i++) {
                int r = m_off + i * 16 + qr;
                a1[i][0] = A1[r * 20 + w0];       a1[i][1] = A1[(r + 8) * 20 + w0];
                a1[i][2] = A1[r * 20 + w0 + 4];   a1[i][3] = A1[(r + 8) * 20 + w0 + 4];
            }
#pragma unroll
            for (int j = 0; j < 8; j++) {
                int n = n_off + j * 8 + qr;
                uint32_t b1[2] = { B1[n * 20 + w0], B1[n * 20 + w0 + 4] };
                uint32_t b2[2] = { B2[n * 20 + w0], B2[n * 20 + w0 + 4] };
#pragma unroll
                for (int i = 0; i < 2; i++) {
                    mma_bf16(acc[i][j], a1[i], b1);
                    mma_bf16(acc[i][j], a1[i], b2);
                }
            }
        }
        __syncthreads();
        if (it + NSTG < KITERS)
            load_stage_emu(sb + ((it + NSTG) % NSTG) * STAGE_B, it + NSTG, m0, bb, dd, h0, tid);
    }

#pragma unroll
    for (int i = 0; i < 2; i++) {
        int r0 = m0 + m_off + i * 16 + qr;
        float b0 = bias[r0], b1v = bias[r0 + 8];
#pragma unroll
        for (int j = 0; j < 8; j++) {
            int c0 = n0 + n_off + j * 8 + qc * 2;
            float2 v0, v1;
            v0.x = fmaxf(acc[i][j][0] + b0, 0.f);
            v0.y = fmaxf(acc[i][j][1] + b0, 0.f);
            v1.x = fmaxf(acc[i][j][2] + b1v, 0.f);
            v1.y = fmaxf(acc[i][j][3] + b1v, 0.f);
            *(float2*)(g_xe + (size_t)r0 * NCOL + c0) = v0;
            *(float2*)(g_xe + (size_t)(r0 + 8) * NCOL + c0) = v1;
        }
    }
}

// ---------------- emu heads: 18 cls rows, dedicated kernel ----------------
__global__ __launch_bounds__(128)
void head18_kernel() {
    __shared__ float w[CLSROWS * 512];
    int t = threadIdx.x;
    for (int i = t; i < CLSROWS * 512; i += 128) w[i] = g_wh[i];
    __syncthreads();
    int n = blockIdx.x * 128 + t;
    float acc[CLSROWS];
#pragma unroll
    for (int r = 0; r < CLSROWS; r++) acc[r] = g_bh[r];
    for (int k = 0; k < 512; k++) {
        float xv = g_xe[(size_t)k * NCOL + n];
#pragma unroll
        for (int r = 0; r < CLSROWS; r++) acc[r] = fmaf(w[r * 512 + k], xv, acc[r]);
    }
#pragma unroll
    for (int r = 0; r < CLSROWS; r++) g_h[(size_t)r * NCOL + n] = acc[r];
}

// ---------------- exact GEMM, 32m x 64n tiles (bit-identical k-ascending fmaf chains) ----------------
__global__ __launch_bounds__(128)
void exact32x64(const float* __restrict__ A, const float* __restrict__ B,
                float* __restrict__ C, const float* __restrict__ bias,
                int M, int N, int K, int doRelu, const int* __restrict__ nlim) {
    if (blockIdx.x * 64 >= *nlim) return;
    __shared__ float As[2][8][32];
    __shared__ float Bs[2][8][64];
    const int tid = threadIdx.x;
    const int m0 = blockIdx.y * 32;
    const int n0 = blockIdx.x * 64;
    const int mg = tid >> 4, ng = tid & 15;
    const int am = tid & 31, akq = (tid >> 5) * 4;
    const int bk = tid >> 4, bn4 = (tid & 15) * 4;

    float acc[4][4];
#pragma unroll
    for (int i = 0; i < 4; i++)
#pragma unroll
        for (int j = 0; j < 4; j++) acc[i][j] = 0.f;

    float4 av = make_float4(0.f, 0.f, 0.f, 0.f), bv;
    {
        if (tid < 64) {
            int gm = m0 + am;
            if (gm < M) av = *(const float4*)(A + (size_t)gm * K + akq);
        }
        bv = *(const float4*)(B + (size_t)bk * N + n0 + bn4);
        if (tid < 64) {
            As[0][akq + 0][am] = av.x; As[0][akq + 1][am] = av.y;
            As[0][akq + 2][am] = av.z; As[0][akq + 3][am] = av.w;
        }
        *(float4*)&Bs[0][bk][bn4] = bv;
    }
    __syncthreads();

    int cur = 0;
    for (int kt = 8; kt < K; kt += 8) {
        av = make_float4(0.f, 0.f, 0.f, 0.f);
        if (tid < 64) {
            int gm = m0 + am;
            if (gm < M) av = *(const float4*)(A + (size_t)gm * K + kt + akq);
        }
        bv = *(const float4*)(B + (size_t)(kt + bk) * N + n0 + bn4);

#pragma unroll
        for (int kk = 0; kk < 8; kk++) {
            float4 a = *(const float4*)&As[cur][kk][mg * 4];
            float4 b = *(const float4*)&Bs[cur][kk][ng * 4];
            acc[0][0] = fmaf(a.x, b.x, acc[0][0]); acc[0][1] = fmaf(a.x, b.y, acc[0][1]);
            acc[0][2] = fmaf(a.x, b.z, acc[0][2]); acc[0][3] = fmaf(a.x, b.w, acc[0][3]);
            acc[1][0] = fmaf(a.y, b.x, acc[1][0]); acc[1][1] = fmaf(a.y, b.y, acc[1][1]);
            acc[1][2] = fmaf(a.y, b.z, acc[1][2]); acc[1][3] = fmaf(a.y, b.w, acc[1][3]);
            acc[2][0] = fmaf(a.z, b.x, acc[2][0]); acc[2][1] = fmaf(a.z, b.y, acc[2][1]);
            acc[2][2] = fmaf(a.z, b.z, acc[2][2]); acc[2][3] = fmaf(a.z, b.w, acc[2][3]);
            acc[3][0] = fmaf(a.w, b.x, acc[3][0]); acc[3][1] = fmaf(a.w, b.y, acc[3][1]);
            acc[3][2] = fmaf(a.w, b.z, acc[3][2]); acc[3][3] = fmaf(a.w, b.w, acc[3][3]);
        }
        int nxt = cur ^ 1;
        if (tid < 64) {
            As[nxt][akq + 0][am] = av.x; As[nxt][akq + 1][am] = av.y;
            As[nxt][akq + 2][am] = av.z; As[nxt][akq + 3][am] = av.w;
        }
        *(float4*)&Bs[nxt][bk][bn4] = bv;
        __syncthreads();
        cur = nxt;
    }
#pragma unroll
    for (int kk = 0; kk < 8; kk++) {
        float4 a = *(const float4*)&As[cur][kk][mg * 4];
        float4 b = *(const float4*)&Bs[cur][kk][ng * 4];
        acc[0][0] = fmaf(a.x, b.x, acc[0][0]); acc[0][1] = fmaf(a.x, b.y, acc[0][1]);
        acc[0][2] = fmaf(a.x, b.z, acc[0][2]); acc[0][3] = fmaf(a.x, b.w, acc[0][3]);
        acc[1][0] = fmaf(a.y, b.x, acc[1][0]); acc[1][1] = fmaf(a.y, b.y, acc[1][1]);
        acc[1][2] = fmaf(a.y, b.z, acc[1][2]); acc[1][3] = fmaf(a.y, b.w, acc[1][3]);
        acc[2][0] = fmaf(a.z, b.x, acc[2][0]); acc[2][1] = fmaf(a.z, b.y, acc[2][1]);
        acc[2][2] = fmaf(a.z, b.z, acc[2][2]); acc[2][3] = fmaf(a.z, b.w, acc[2][3]);
        acc[3][0] = fmaf(a.w, b.x, acc[3][0]); acc[3][1] = fmaf(a.w, b.y, acc[3][1]);
        acc[3][2] = fmaf(a.w, b.z, acc[3][2]); acc[3][3] = fmaf(a.w, b.w, acc[3][3]);
    }

#pragma unroll
    for (int i = 0; i < 4; i++) {
        int gm = m0 + mg * 4 + i;
        if (gm >= M) continue;
        float bb = bias[gm];
        float4 v;
        v.x = acc[i][0] + bb; v.y = acc[i][1] + bb;
        v.z = acc[i][2] + bb; v.w = acc[i][3] + bb;
        if (doRelu) {
            v.x = fmaxf(v.x, 0.f); v.y = fmaxf(v.y, 0.f);
            v.z = fmaxf(v.z, 0.f); v.w = fmaxf(v.w, 0.f);
        }
        *(float4*)(C + (size_t)gm * N + n0 + ng * 4) = v;
    }
}

// ---------------- pack head weights ----------------
__global__ void pack_head(const float* __restrict__ Wc, const float* __restrict__ bc,
                          const float* __restrict__ Wb, const float* __restrict__ bb) {
    int idx = blockIdx.x * 256 + threadIdx.x;
    if (idx < HROWS * 512) {
        int row = idx / 512, col = idx % 512;
        g_wh[idx] = (row < 18) ? Wc[row * 512 + col] : Wb[(row - 18) * 512 + col];
    }
    if (idx < HROWS) g_bh[idx] = (idx < 18) ? bc[idx] : bb[idx - 18];
}

// ---------------- emu scores + clear ----------------
__global__ void escore_kernel() {
    int idx = blockIdx.x * 256 + threadIdx.x;
    if (idx < BATCH * POS) g_pflag[idx] = 0;
    if (idx >= BATCH * NPROP) return;
    g_scores[idx] = 0.f;
    int b = idx / NPROP;
    int i = idx - b * NPROP;
    int pos = i / NANCH;
    int a = i - pos * NANCH;
    int n = b * POS + pos;
    float l0 = g_h[(size_t)a * NCOL + n];
    float l1 = g_h[(size_t)(NANCH + a) * NCOL + n];
    float mx = fmaxf(l0, l1);
    float e0 = expf(l0 - mx), e1 = expf(l1 - mx);
    g_escore[idx] = e1 / (e0 + e1);
}

// ---------------- emu cutoff (2048th) ----------------
__global__ __launch_bounds__(1024)
void cutoff_kernel() {
    const int b = blockIdx.x;
    const int tid = threadIdx.x;
    const float* sc = g_escore + (size_t)b * NPROP;
    __shared__ unsigned sh_hist[256];
    __shared__ unsigned sh_prefix;
    __shared__ int sh_need;
    if (tid == 0) { sh_prefix = 0; sh_need = PRE_NMS; }
    __syncthreads();
    for (int p = 3; p >= 0; p--) {
        for (int v = tid; v < 256; v += 1024) sh_hist[v] = 0;
        __syncthreads();
        unsigned pref = sh_prefix;
        unsigned pm = (p == 3) ? 0u : (0xFFFFFFFFu << ((p + 1) * 8));
        for (int i = tid; i < NPROP; i += 1024) {
            unsigned rk = rkey(sc[i]);
            if ((rk & pm) == pref) atomicAdd(&sh_hist[(rk >> (p * 8)) & 255], 1u);
        }
        __syncthreads();
        if (tid == 0) {
            int need = sh_need;
            unsigned acc = 0;
            for (int v = 0; v < 256; v++) {
                unsigned c = sh_hist[v];
                if (need <= (int)(acc + c)) {
                    sh_prefix = pref | ((unsigned)v << (p * 8));
                    sh_need = need - (int)acc;
                    break;
                }
                acc += c;
            }
        }
        __syncthreads();
    }
    if (tid == 0) {
        unsigned m = ~sh_prefix;
        float cf = __uint_as_float(m & 0x7FFFFFFFu);
        g_thr[b] = cf - MARGIN;
    }
}

// ---------------- candidate flags ----------------
__global__ void flag_kernel() {
    int idx = blockIdx.x * 256 + threadIdx.x;
    if (idx >= BATCH * NPROP) return;
    int b = idx / NPROP;
    if (g_escore[idx] >= g_thr[b]) {
        int pos = (idx - b * NPROP) / NANCH;
        g_pflag[b * POS + pos] = 1;
    }
}

// ---------------- compaction ----------------
__global__ __launch_bounds__(1024)
void compact_kernel() {
    __shared__ int warp_sums[32];
    __shared__ int base_off;
    int tid = threadIdx.x;
    int lane = tid & 31, wrp = tid >> 5;
    if (tid == 0) base_off = 0;
    __syncthreads();
    for (int b = 0; b < BATCH; b++) {
        int cnt = 0;
        int mypos[8];
#pragma unroll
        for (int u = 0; u < 8; u++) {
            int pos = tid * 8 + u;
            if (g_pflag[b * POS + pos]) mypos[cnt++] = pos;
        }
        int v = cnt;
#pragma unroll
        for (int o = 1; o < 32; o <<= 1) {
            int t = __shfl_up_sync(0xffffffffu, v, o);
            if (lane >= o) v += t;
        }
        if (lane == 31) warp_sums[wrp] = v;
        __syncthreads();
        if (wrp == 0) {
            int wv = warp_sums[lane];
#pragma unroll
            for (int o = 1; o < 32; o <<= 1) {
                int t = __shfl_up_sync(0xffffffffu, wv, o);
                if (lane >= o) wv += t;
            }
            warp_sums[lane] = wv;
        }
        __syncthreads();
        int excl = v - cnt + (wrp ? warp_sums[wrp - 1] : 0);
        int bo = base_off;
        for (int u = 0; u < cnt; u++) {
            int slot = bo + excl + u;
            if (slot < CCAP) g_plist[slot] = b * POS + mypos[u];
        }
        __syncthreads();
        if (tid == 0) {
            int tot = warp_sums[31];
            int nb = base_off + tot; if (nb > CCAP) nb = CCAP;
            if (b == 0) g_nc[0] = nb;
            base_off = nb;
            if (b == BATCH - 1) {
                g_nc[1] = base_off;
                g_nc[2] = (base_off + 63) & ~63;
            }
        }
        __syncthreads();
    }
}

// ---------------- gather (coalesced writes) ----------------
__global__ void gather_kernel(const float* __restrict__ bf) {
    int j0 = blockIdx.x * 32;
    if (j0 >= g_nc[1]) return;
    int jl = threadIdx.x & 31;
    int kl = threadIdx.x >> 5;
    int j = j0 + jl;
    int n = g_plist[j];
    int b = n >> 13, pos = n & (POS - 1);
#pragma unroll
    for (int kk = 0; kk < 16; kk++) {
        int k = blockIdx.y * 128 + kl * 16 + kk;
        g_colc[(size_t)k * CW + j] = im2col_val(bf, b, pos, k);
    }
}

// ---------------- exact decode for candidates ----------------
__global__ void decode_cand_kernel(const float* __restrict__ im_info) {
    int idx = blockIdx.x * 256 + threadIdx.x;
    int cidx = idx / NANCH;
    if (cidx >= g_nc[1]) return;
    int a = idx - cidx * NANCH;
    int n = g_plist[cidx];
    int b = n >> 13, pos = n & (POS - 1);
    int i = pos * NANCH + a;

    float l0 = g_hc[(size_t)a * CW + cidx];
    float l1 = g_hc[(size_t)(NANCH + a) * CW + cidx];
    float mx = fmaxf(l0, l1);
    float e0 = expf(l0 - mx), e1 = expf(l1 - mx);
    g_scores[(size_t)b * NPROP + i] = e1 / (e0 + e1);

    const float* hd = g_hc + (size_t)(18 + a * 6) * CW + cidx;
    float dx = hd[0 * (size_t)CW], dy = hd[1 * (size_t)CW], dz = hd[2 * (size_t)CW];
    float dw = hd[3 * (size_t)CW], dh = hd[4 * (size_t)CW], dd = hd[5 * (size_t)CW];

    int wp = pos & 31, hp = (pos >> 5) & 31, dp = pos >> 10;
    float s = 4.f * (float)(1 << (a % 3));
    float r = 0.5f * (float)(1 << (a / 3));
    float wsz = 8.f * s;
    float dsz = 8.f * s * r;
    const float ctr = 3.5f;
    float sx = wp * 8.f, sy = hp * 8.f, sz = dp * 8.f;

    float x1 = sx + ctr - 0.5f * (wsz - 1.f), x2 = sx + ctr + 0.5f * (wsz - 1.f);
    float y1 = sy + ctr - 0.5f * (wsz - 1.f), y2 = sy + ctr + 0.5f * (wsz - 1.f);
    float z1 = sz + ctr - 0.5f * (dsz - 1.f), z2 = sz + ctr + 0.5f * (dsz - 1.f);

    float aw = x2 - x1 + 1.f, ah = y2 - y1 + 1.f, ad = z2 - z1 + 1.f;
    float cx = x1 + 0.5f * aw, cy = y1 + 0.5f * ah, cz = z1 + 0.5f * ad;

    float pcx = dx * aw + cx, pcy = dy * ah + cy, pcz = dz * ad + cz;
    float pw = expf(dw) * aw, ph = expf(dh) * ah, pd = expf(dd) * ad;

    float ox1 = pcx - 0.5f * pw, oy1 = pcy - 0.5f * ph, oz1 = pcz - 0.5f * pd;
    float ox2 = pcx + 0.5f * pw, oy2 = pcy + 0.5f * ph, oz2 = pcz + 0.5f * pd;

    float hix = im_info[b * 3 + 2] - 1.f;
    float hiy = im_info[b * 3 + 1] - 1.f;
    float hiz = im_info[b * 3 + 0] - 1.f;
    ox1 = fminf(fmaxf(ox1, 0.f), hix); ox2 = fminf(fmaxf(ox2, 0.f), hix);
    oy1 = fminf(fmaxf(oy1, 0.f), hiy); oy2 = fminf(fmaxf(oy2, 0.f), hiy);
    oz1 = fminf(fmaxf(oz1, 0.f), hiz); oz2 = fminf(fmaxf(oz2, 0.f), hiz);

    float* ob = g_boxes + ((size_t)b * NPROP + i) * 6;
    ob[0] = ox1; ob[1] = oy1; ob[2] = oz1; ob[3] = ox2; ob[4] = oy2; ob[5] = oz2;
}

// ---------------- top-2048 select (exact jax top_k order) ----------------
__global__ __launch_bounds__(1024)
void select_topk_kernel() {
    const int b = blockIdx.x;
    const int tid = threadIdx.x;
    const float* sc = g_scores + (size_t)b * NPROP;

    __shared__ unsigned sh_hist[256];
    __shared__ unsigned sh_prefix;
    __shared__ int sh_need;
    __shared__ int sh_cnt;
    __shared__ unsigned long long s[4096];

    if (tid == 0) { sh_prefix = 0; sh_need = PRE_NMS; }
    __syncthreads();

    for (int p = 3; p >= 0; p--) {
        for (int v = tid; v < 256; v += 1024) sh_hist[v] = 0;
        __syncthreads();
        unsigned pref = sh_prefix;
        unsigned pm = (p == 3) ? 0u : (0xFFFFFFFFu << ((p + 1) * 8));
        for (int i = tid; i < NPROP; i += 1024) {
            unsigned rk = rkey(sc[i]);
            if ((rk & pm) == pref) atomicAdd(&sh_hist[(rk >> (p * 8)) & 255], 1u);
        }
        __syncthreads();
        if (tid == 0) {
            int need = sh_need;
            unsigned acc = 0;
            for (int v = 0; v < 256; v++) {
                unsigned c = sh_hist[v];
                if (need <= (int)(acc + c)) {
                    sh_prefix = pref | ((unsigned)v << (p * 8));
                    sh_need = need - (int)acc;
                    break;
                }
                acc += c;
            }
        }
        __syncthreads();
    }
    unsigned cutoff = sh_prefix;
    if (tid == 0) sh_cnt = 0;
    __syncthreads();

    for (int i = tid; i < NPROP; i += 1024) {
        unsigned rk = rkey(sc[i]);
        if (rk <= cutoff) {
            int posn = atomicAdd(&sh_cnt, 1);
            if (posn < 4096)
                g_cand[b][posn] = ((unsigned long long)rk << 32) | (unsigned)i;
        }
    }
    __syncthreads();
    int total = sh_cnt; if (total > 4096) total = 4096;
    for (int i = tid; i < 4096; i += 1024)
        s[i] = (i < total) ? g_cand[b][i] : 0xFFFFFFFFFFFFFFFFull;
    __syncthreads();

    for (int k = 2; k <= 4096; k <<= 1) {
        for (int j = k >> 1; j > 0; j >>= 1) {
            for (int i = tid; i < 4096; i += 1024) {
                int l = i ^ j;
                if (l > i) {
                    unsigned long long a = s[i], c = s[l];
                    bool sw = ((i & k) == 0) ? (a > c) : (a < c);
                    if (sw) { s[i] = c; s[l] = a; }
                }
            }
            __syncthreads();
        }
    }

    for (int r2 = tid; r2 < PRE_NMS; r2 += 1024) {
        unsigned idx = (unsigned)(s[r2] & 0xFFFFFFFFull);
        const float* src = g_boxes + ((size_t)b * NPROP + idx) * 6;
        float* dst = g_sboxes + ((size_t)b * PRE_NMS + r2) * 6;
#pragma unroll
        for (int c = 0; c < 6; c++) dst[c] = src[c];
    }
}

// ---------------- NMS bitmask ----------------
__global__ void nms_mask_kernel() {
    int b = blockIdx.z, jb = blockIdx.x, ib = blockIdx.y, t = threadIdx.x;
    __shared__ float cb[64][6];
    const float* sb = g_sboxes + (size_t)b * PRE_NMS * 6;
    {
        const float* p = sb + (size_t)(jb * 64 + t) * 6;
#pragma unroll
        for (int c = 0; c < 6; c++) cb[t][c] = p[c];
    }
    __syncthreads();

    int i = ib * 64 + t;
    const float* p = sb + (size_t)i * 6;
    float x1 = p[0], y1 = p[1], z1 = p[2], x2 = p[3], y2 = p[4], z2 = p[5];
    float vi = (x2 - x1 + 1.f) * (y2 - y1 + 1.f) * (z2 - z1 + 1.f);
    unsigned long long bits = 0ull;
#pragma unroll 4
    for (int jj = 0; jj < 64; jj++) {
        float ix = fmaxf(fminf(x2, cb[jj][3]) - fmaxf(x1, cb[jj][0]) + 1.f, 0.f);
        float iy = fmaxf(fminf(y2, cb[jj][4]) - fmaxf(y1, cb[jj][1]) + 1.f, 0.f);
        float iz = fmaxf(fminf(z2, cb[jj][5]) - fmaxf(z1, cb[jj][2]) + 1.f, 0.f);
        float inter = ix * iy * iz;
        float vj = (cb[jj][3] - cb[jj][0] + 1.f) * (cb[jj][4] - cb[jj][1] + 1.f)
                 * (cb[jj][5] - cb[jj][2] + 1.f);
        float iou = inter / (vi + vj - inter);
        if (iou > NMS_TH) bits |= (1ull << jj);
    }
    g_mask[((size_t)b * PRE_NMS + i) * 32 + jb] = bits;
}

// ---------------- sequential keep-scan + output (16-deep prefetch ring) ----------------
__global__ void nms_scan_kernel(float* __restrict__ out) {
    int b = blockIdx.x;
    int lane = threadIdx.x;
    __shared__ unsigned short keep[POST_NMS];
    unsigned long long rem = 0ull;
    int nk = 0;
    const unsigned long long* mb = g_mask + (size_t)b * PRE_NMS * 32;

    unsigned long long pf[16];
#pragma unroll
    for (int u = 0; u < 16; u++) pf[u] = mb[(size_t)u * 32 + lane];

    for (int base = 0; base < PRE_NMS; base += 16) {
#pragma unroll
        for (int u = 0; u < 16; u++) {
            int i = base + u;
            unsigned long long w = __shfl_sync(0xffffffffu, rem, i >> 6);
            unsigned long long m = pf[u];
            int nx = i + 16;
            if (nx < PRE_NMS) pf[u] = mb[(size_t)nx * 32 + lane];
            if (!((w >> (i & 63)) & 1ull)) {
                if (lane == 0 && nk < POST_NMS) keep[nk] = (unsigned short)i;
                nk++;
                rem |= m;
            }
        }
    }
    __syncwarp();
    for (int r = lane; r < POST_NMS; r += 32) {
        float* o = out + ((size_t)b * POST_NMS + r) * 7;
        o[0] = (float)b;
        if (r < nk) {
            int i = keep[r];
            const float* bx = g_sboxes + ((size_t)b * PRE_NMS + i) * 6;
#pragma unroll
            for (int c = 0; c < 6; c++) o[1 + c] = bx[c];
        } else {
#pragma unroll
            for (int c = 0; c < 6; c++) o[1 + c] = 0.f;
        }
    }
}

// ---------------- launch ----------------
extern "C" void kernel_launch(void* const* d_in, const int* in_sizes, int n_in,
                              void* d_out, int out_size) {
    const float* base_feat = (const float*)d_in[0];
    const float* im_info   = (const float*)d_in[1];
    const float* W_conv    = (const float*)d_in[4];
    const float* b_conv    = (const float*)d_in[5];
    const float* W_cls     = (const float*)d_in[6];
    const float* b_cls     = (const float*)d_in[7];
    const float* W_bbox    = (const float*)d_in[8];
    const float* b_bbox    = (const float*)d_in[9];
    float* out = (float*)d_out;

    float *p_wh, *p_bh, *p_colc, *p_xc, *p_hc;
    int* p_nc;
    cudaGetSymbolAddress((void**)&p_wh,   g_wh);
    cudaGetSymbolAddress((void**)&p_bh,   g_bh);
    cudaGetSymbolAddress((void**)&p_colc, g_colc);
    cudaGetSymbolAddress((void**)&p_xc,   g_xc);
    cudaGetSymbolAddress((void**)&p_hc,   g_hc);
    cudaGetSymbolAddress((void**)&p_nc,   g_nc);

    cudaFuncSetAttribute(conv_emu_kernel, cudaFuncAttributeMaxDynamicSharedMemorySize, SMEM_EMU);

    zero_fp_kernel<<<(int)((FPAD / 8 + 255) / 256), 256>>>();
    tsplit_kernel<<<BATCH * DD * HH, 256>>>(base_feat);
    a_reord_kernel<<<(COUT * KDIM + 255) / 256, 256>>>(W_conv);
    {   // emu conv (implicit im2col from L2-resident padded features)
        dim3 grid(COUT / 128, NCOL / 128);
        conv_emu_kernel<<<grid, 256, SMEM_EMU>>>(b_conv);
    }
    pack_head<<<(HROWS * 512 + 255) / 256, 256>>>(W_cls, b_cls, W_bbox, b_bbox);
    head18_kernel<<<NCOL / 128, 128>>>();
    escore_kernel<<<(BATCH * NPROP + 255) / 256, 256>>>();
    cutoff_kernel<<<BATCH, 1024>>>();
    flag_kernel<<<(BATCH * NPROP + 255) / 256, 256>>>();
    compact_kernel<<<1, 1024>>>();
    {
        dim3 grid(CCAP / 32, 27);
        gather_kernel<<<grid, 256>>>(base_feat);
    }
    {   // exact conv on compacted columns (32x64 tiles, R1-identical numerics)
        dim3 grid(CW / 64, COUT / 32);
        exact32x64<<<grid, 128>>>(W_conv, p_colc, p_xc, b_conv, COUT, CW, KDIM, 1, p_nc + 2);
    }
    {   // exact heads on compacted columns
        dim3 grid(CW / 64, (HROWS + 31) / 32);
        exact32x64<<<grid, 128>>>(p_wh, p_xc, p_hc, p_bh, HROWS, CW, 512, 0, p_nc + 2);
    }
    decode_cand_kernel<<<(CCAP * NANCH + 255) / 256, 256>>>(im_info);
    select_topk_kernel<<<BATCH, 1024>>>();
    {
        dim3 grid(PRE_NMS / 64, PRE_NMS / 64, BATCH);
        nms_mask_kernel<<<grid, 64>>>();
    }
    nms_scan_kernel<<<BATCH, 32>>>(out);
}

// round 15
// speedup vs baseline: 1.1759x; 1.1115x over previous
#include <cuda_runtime.h>
#include <cuda_bf16.h>
#include <math.h>
#include <stdint.h>

// ---------------- problem constants ----------------
#define BATCH   2
#define CIN     128
#define COUT    512
#define DD      8
#define HH      32
#define WW      32
#define POS     (DD*HH*WW)          // 8192
#define NCOL    (BATCH*POS)         // 16384
#define KDIM    (CIN*27)            // 3456
#define NANCH   9
#define NPROP   (POS*NANCH)         // 73728 per batch
#define PRE_NMS 2048
#define POST_NMS 300
#define NMS_TH  0.7f
#define HROWS   72
#define CLSROWS 18
#define MARGIN  8e-3f
#define CCAP    8192
#define CW      8192

// emu conv tiling (A bf16 x B bf16, single term), K reordered as (off, c)
#define TILE_K    32
#define KITERS    (KDIM/TILE_K)     // 108
#define PLANE_W   (128*20)
#define STAGE_W   (2*PLANE_W)       // A, B1
#define STAGE_B   (STAGE_W*4)       // 20480 bytes
#define NSTG      3
#define SMEM_EMU  (NSTG*STAGE_B)    // 61440

// padded transposed feature map: [B][D+2][H+2][W+2][C]
#define FPD     (DD+2)
#define FPH     (HH+2)
#define FPW     (WW+2)
#define FPAD    ((size_t)BATCH*FPD*FPH*FPW*CIN)

// ---------------- static scratch ----------------
__device__ __align__(128) __nv_bfloat16 g_fp1[FPAD];
__device__ __align__(128) __nv_bfloat16 g_ar [(size_t)COUT * KDIM];
__device__ float g_xe  [(size_t)COUT * NCOL];
__device__ float g_h   [(size_t)CLSROWS * NCOL];
__device__ float g_colc[(size_t)KDIM * CW];
__device__ float g_xc  [(size_t)COUT * CW];
__device__ float g_hc  [(size_t)HROWS * CW];
__device__ float g_wh  [HROWS * 512];
__device__ float g_bh  [HROWS];
__device__ float g_escore[BATCH * NPROP];
__device__ float g_thr[BATCH];
__device__ int   g_pflag[BATCH * POS];
__device__ int   g_plist[CCAP];
__device__ int   g_nc[4];
__device__ float g_scores[BATCH * NPROP];
__device__ float g_boxes [(size_t)BATCH * NPROP * 6];
__device__ unsigned long long g_cand[BATCH][4096];
__device__ float g_sboxes[(size_t)BATCH * PRE_NMS * 6];
__device__ unsigned long long g_mask[(size_t)BATCH * PRE_NMS * 32];

// ---------------- helpers ----------------
__device__ __forceinline__ uint32_t smem_u32(const void* p) {
    uint32_t a;
    asm("{ .reg .u64 t; cvta.to.shared.u64 t, %1; cvt.u32.u64 %0, t; }" : "=r"(a) : "l"(p));
    return a;
}
__device__ __forceinline__ void cp_async16(uint32_t dst, const void* src) {
    asm volatile("cp.async.cg.shared.global [%0], [%1], 16;" :: "r"(dst), "l"(src));
}
__device__ __forceinline__ void cp_commit() { asm volatile("cp.async.commit_group;" ::: "memory"); }
__device__ __forceinline__ void cp_wait2()  { asm volatile("cp.async.wait_group 2;" ::: "memory"); }
__device__ __forceinline__ void cp_wait1()  { asm volatile("cp.async.wait_group 1;" ::: "memory"); }
__device__ __forceinline__ void cp_wait0()  { asm volatile("cp.async.wait_group 0;" ::: "memory"); }

__device__ __forceinline__ void mma_bf16(float c[4], const uint32_t a[4], const uint32_t b[2]) {
    asm volatile("mma.sync.aligned.m16n8k16.row.col.f32.bf16.bf16.f32 "
        "{%0,%1,%2,%3}, {%4,%5,%6,%7}, {%8,%9}, {%0,%1,%2,%3};"
        : "+f"(c[0]), "+f"(c[1]), "+f"(c[2]), "+f"(c[3])
        : "r"(a[0]), "r"(a[1]), "r"(a[2]), "r"(a[3]), "r"(b[0]), "r"(b[1]));
}
__device__ __forceinline__ unsigned int rkey(float f) {
    unsigned u = __float_as_uint(f);
    u = (u & 0x80000000u) ? ~u : (u | 0x80000000u);
    return ~u;
}

// ---------------- im2col value (exact path; original K order c*27+off) ----------------
__device__ __forceinline__ float im2col_val(const float* __restrict__ bf, int b, int pos, int k) {
    int c = k / 27; int rem = k - c * 27;
    int kd = rem / 9, kh = (rem % 9) / 3, kw = rem % 3;
    int d = pos >> 10, h = (pos >> 5) & 31, w = pos & 31;
    int zd = d + kd - 1, zh = h + kh - 1, zw = w + kw - 1;
    if ((unsigned)zd < DD && (unsigned)zh < HH && (unsigned)zw < WW)
        return bf[(((size_t)(b * CIN + c) * DD + zd) * HH + zh) * WW + zw];
    return 0.f;
}

// ---------------- zero padded feature map ----------------
__global__ void zero_fp_kernel() {
    size_t idx = (size_t)(blockIdx.x * 256 + threadIdx.x) * 8;
    if (idx < FPAD)
        *(uint4*)(g_fp1 + idx) = make_uint4(0, 0, 0, 0);
}

// ---------------- transpose + bf16 round ----------------
__global__ void tsplit_kernel(const float* __restrict__ bf) {
    __shared__ float tile[128][33];
    int blk = blockIdx.x;
    int b = blk >> 8;
    int d = (blk >> 5) & 7;
    int h = blk & 31;
    int t = threadIdx.x;

    int w = t & 31, cr = t >> 5;
#pragma unroll
    for (int i = 0; i < 16; i++) {
        int c = i * 8 + cr;
        tile[c][w] = bf[(((size_t)(b * CIN + c) * DD + d) << 10) + h * 32 + w];
    }
    __syncthreads();

    int c2 = t & 127, wr = t >> 7;
    size_t obase = ((((size_t)b * FPD + d + 1) * FPH + h + 1) * FPW + 1) * 128;
#pragma unroll
    for (int i = 0; i < 16; i++) {
        int w2 = i * 2 + wr;
        g_fp1[obase + (size_t)w2 * 128 + c2] = __float2bfloat16_rn(tile[c2][w2]);
    }
}

// ---------------- weight reorder to k=(off, c), bf16 ----------------
__global__ void a_reord_kernel(const float* __restrict__ Wc) {
    int idx = blockIdx.x * 256 + threadIdx.x;
    if (idx >= COUT * KDIM) return;
    int m = idx / KDIM, k = idx - m * KDIM;
    int off = k >> 7, c = k & 127;
    g_ar[idx] = __float2bfloat16_rn(Wc[(size_t)m * KDIM + c * 27 + off]);
}

// ---------------- emu conv: implicit im2col, A bf16 x B bf16 ----------------
__device__ __forceinline__ void load_stage_emu(uint32_t sbase, int it, int m0,
                                               int bb, int dd, int h0, int tid) {
    int k0 = it * TILE_K;
    int off = k0 >> 7;
    int c0  = k0 & 127;
    int kd = off / 9; int r9 = off - kd * 9;
    int kh = r9 / 3;  int kw = r9 - kh * 3;

#pragma unroll
    for (int i = 0; i < 2; i++) {
        int cwp = i * 256 + tid;
        int row = cwp >> 2, quad = cwp & 3;
        uint32_t doff = (uint32_t)(row * 80 + quad * 16);
        cp_async16(sbase + doff, g_ar + (size_t)(m0 + row) * KDIM + k0 + quad * 8);
    }
#pragma unroll
    for (int i = 0; i < 2; i++) {
        int cwp = i * 256 + tid;
        int row = cwp >> 2, quad = cwp & 3;
        int h = h0 + (row >> 5);
        int w = row & 31;
        size_t base = ((((size_t)bb * FPD + dd + kd) * FPH + h + kh) * FPW + (w + kw)) * 128
                    + c0 + quad * 8;
        uint32_t doff = (uint32_t)(PLANE_W * 4 + row * 80 + quad * 16);
        cp_async16(sbase + doff, g_fp1 + base);
    }
    cp_commit();
}

__global__ __launch_bounds__(256)
void conv_emu_kernel(const float* __restrict__ bias) {
    extern __shared__ __align__(16) uint32_t smem[];
    const int tid  = threadIdx.x;
    const int wid  = tid >> 5;
    const int lane = tid & 31;
    const int m0 = blockIdx.x * 128;
    const int n0 = blockIdx.y * 128;
    const int m_off = (wid >> 1) * 32;
    const int n_off = (wid & 1) * 64;
    const int qr = lane >> 2, qc = lane & 3;
    uint32_t sb = smem_u32(smem);

    const int bb = n0 >> 13;
    const int pos0 = n0 & (POS - 1);
    const int dd = pos0 >> 10;
    const int h0 = (pos0 >> 5) & 31;

    float acc[2][8][4];
#pragma unroll
    for (int i = 0; i < 2; i++)
#pragma unroll
        for (int j = 0; j < 8; j++)
#pragma unroll
            for (int t = 0; t < 4; t++) acc[i][j][t] = 0.f;

    load_stage_emu(sb, 0, m0, bb, dd, h0, tid);
    load_stage_emu(sb + STAGE_B, 1, m0, bb, dd, h0, tid);
    load_stage_emu(sb + 2 * STAGE_B, 2, m0, bb, dd, h0, tid);

    for (int it = 0; it < KITERS; it++) {
        if (it < KITERS - 2) cp_wait2();
        else if (it < KITERS - 1) cp_wait1();
        else cp_wait0();
        __syncthreads();

        const uint32_t* S = smem + (it % NSTG) * STAGE_W;
        const uint32_t* A1 = S;
        const uint32_t* B1 = S + PLANE_W;

#pragma unroll
        for (int q = 0; q < 2; q++) {
            int w0 = q * 8 + qc;
            uint32_t a1[2][4];
#pragma unroll
            for (int i = 0; i < 2; i++) {
                int r = m_off + i * 16 + qr;
                a1[i][0] = A1[r * 20 + w0];       a1[i][1] = A1[(r + 8) * 20 + w0];
                a1[i][2] = A1[r * 20 + w0 + 4];   a1[i][3] = A1[(r + 8) * 20 + w0 + 4];
            }
#pragma unroll
            for (int j = 0; j < 8; j++) {
                int n = n_off + j * 8 + qr;
                uint32_t b1[2] = { B1[n * 20 + w0], B1[n * 20 + w0 + 4] };
#pragma unroll
                for (int i = 0; i < 2; i++)
                    mma_bf16(acc[i][j], a1[i], b1);
            }
        }
        __syncthreads();
        if (it + NSTG < KITERS)
            load_stage_emu(sb + ((it + NSTG) % NSTG) * STAGE_B, it + NSTG, m0, bb, dd, h0, tid);
    }

#pragma unroll
    for (int i = 0; i < 2; i++) {
        int r0 = m0 + m_off + i * 16 + qr;
        float b0 = bias[r0], b1v = bias[r0 + 8];
#pragma unroll
        for (int j = 0; j < 8; j++) {
            int c0 = n0 + n_off + j * 8 + qc * 2;
            float2 v0, v1;
            v0.x = fmaxf(acc[i][j][0] + b0, 0.f);
            v0.y = fmaxf(acc[i][j][1] + b0, 0.f);
            v1.x = fmaxf(acc[i][j][2] + b1v, 0.f);
            v1.y = fmaxf(acc[i][j][3] + b1v, 0.f);
            *(float2*)(g_xe + (size_t)r0 * NCOL + c0) = v0;
            *(float2*)(g_xe + (size_t)(r0 + 8) * NCOL + c0) = v1;
        }
    }
}

// ---------------- emu heads: 18 cls rows, dedicated kernel ----------------
__global__ __launch_bounds__(128)
void head18_kernel() {
    __shared__ float w[CLSROWS * 512];
    int t = threadIdx.x;
    for (int i = t; i < CLSROWS * 512; i += 128) w[i] = g_wh[i];
    __syncthreads();
    int n = blockIdx.x * 128 + t;
    float acc[CLSROWS];
#pragma unroll
    for (int r = 0; r < CLSROWS; r++) acc[r] = g_bh[r];
    for (int k = 0; k < 512; k++) {
        float xv = g_xe[(size_t)k * NCOL + n];
#pragma unroll
        for (int r = 0; r < CLSROWS; r++) acc[r] = fmaf(w[r * 512 + k], xv, acc[r]);
    }
#pragma unroll
    for (int r = 0; r < CLSROWS; r++) g_h[(size_t)r * NCOL + n] = acc[r];
}

// ---------------- exact GEMM, 32m x 64n tiles (bit-identical k-ascending fmaf chains) ----------------
__global__ __launch_bounds__(128)
void exact32x64(const float* __restrict__ A, const float* __restrict__ B,
                float* __restrict__ C, const float* __restrict__ bias,
                int M, int N, int K, int doRelu, const int* __restrict__ nlim) {
    if (blockIdx.x * 64 >= *nlim) return;
    __shared__ float As[2][8][32];
    __shared__ float Bs[2][8][64];
    const int tid = threadIdx.x;
    const int m0 = blockIdx.y * 32;
    const int n0 = blockIdx.x * 64;
    const int mg = tid >> 4, ng = tid & 15;
    const int am = tid & 31, akq = (tid >> 5) * 4;
    const int bk = tid >> 4, bn4 = (tid & 15) * 4;

    float acc[4][4];
#pragma unroll
    for (int i = 0; i < 4; i++)
#pragma unroll
        for (int j = 0; j < 4; j++) acc[i][j] = 0.f;

    float4 av = make_float4(0.f, 0.f, 0.f, 0.f), bv;
    {
        if (tid < 64) {
            int gm = m0 + am;
            if (gm < M) av = *(const float4*)(A + (size_t)gm * K + akq);
        }
        bv = *(const float4*)(B + (size_t)bk * N + n0 + bn4);
        if (tid < 64) {
            As[0][akq + 0][am] = av.x; As[0][akq + 1][am] = av.y;
            As[0][akq + 2][am] = av.z; As[0][akq + 3][am] = av.w;
        }
        *(float4*)&Bs[0][bk][bn4] = bv;
    }
    __syncthreads();

    int cur = 0;
    for (int kt = 8; kt < K; kt += 8) {
        av = make_float4(0.f, 0.f, 0.f, 0.f);
        if (tid < 64) {
            int gm = m0 + am;
            if (gm < M) av = *(const float4*)(A + (size_t)gm * K + kt + akq);
        }
        bv = *(const float4*)(B + (size_t)(kt + bk) * N + n0 + bn4);

#pragma unroll
        for (int kk = 0; kk < 8; kk++) {
            float4 a = *(const float4*)&As[cur][kk][mg * 4];
            float4 b = *(const float4*)&Bs[cur][kk][ng * 4];
            acc[0][0] = fmaf(a.x, b.x, acc[0][0]); acc[0][1] = fmaf(a.x, b.y, acc[0][1]);
            acc[0][2] = fmaf(a.x, b.z, acc[0][2]); acc[0][3] = fmaf(a.x, b.w, acc[0][3]);
            acc[1][0] = fmaf(a.y, b.x, acc[1][0]); acc[1][1] = fmaf(a.y, b.y, acc[1][1]);
            acc[1][2] = fmaf(a.y, b.z, acc[1][2]); acc[1][3] = fmaf(a.y, b.w, acc[1][3]);
            acc[2][0] = fmaf(a.z, b.x, acc[2][0]); acc[2][1] = fmaf(a.z, b.y, acc[2][1]);
            acc[2][2] = fmaf(a.z, b.z, acc[2][2]); acc[2][3] = fmaf(a.z, b.w, acc[2][3]);
            acc[3][0] = fmaf(a.w, b.x, acc[3][0]); acc[3][1] = fmaf(a.w, b.y, acc[3][1]);
            acc[3][2] = fmaf(a.w, b.z, acc[3][2]); acc[3][3] = fmaf(a.w, b.w, acc[3][3]);
        }
        int nxt = cur ^ 1;
        if (tid < 64) {
            As[nxt][akq + 0][am] = av.x; As[nxt][akq + 1][am] = av.y;
            As[nxt][akq + 2][am] = av.z; As[nxt][akq + 3][am] = av.w;
        }
        *(float4*)&Bs[nxt][bk][bn4] = bv;
        __syncthreads();
        cur = nxt;
    }
#pragma unroll
    for (int kk = 0; kk < 8; kk++) {
        float4 a = *(const float4*)&As[cur][kk][mg * 4];
        float4 b = *(const float4*)&Bs[cur][kk][ng * 4];
        acc[0][0] = fmaf(a.x, b.x, acc[0][0]); acc[0][1] = fmaf(a.x, b.y, acc[0][1]);
        acc[0][2] = fmaf(a.x, b.z, acc[0][2]); acc[0][3] = fmaf(a.x, b.w, acc[0][3]);
        acc[1][0] = fmaf(a.y, b.x, acc[1][0]); acc[1][1] = fmaf(a.y, b.y, acc[1][1]);
        acc[1][2] = fmaf(a.y, b.z, acc[1][2]); acc[1][3] = fmaf(a.y, b.w, acc[1][3]);
        acc[2][0] = fmaf(a.z, b.x, acc[2][0]); acc[2][1] = fmaf(a.z, b.y, acc[2][1]);
        acc[2][2] = fmaf(a.z, b.z, acc[2][2]); acc[2][3] = fmaf(a.z, b.w, acc[2][3]);
        acc[3][0] = fmaf(a.w, b.x, acc[3][0]); acc[3][1] = fmaf(a.w, b.y, acc[3][1]);
        acc[3][2] = fmaf(a.w, b.z, acc[3][2]); acc[3][3] = fmaf(a.w, b.w, acc[3][3]);
    }

#pragma unroll
    for (int i = 0; i < 4; i++) {
        int gm = m0 + mg * 4 + i;
        if (gm >= M) continue;
        float bb = bias[gm];
        float4 v;
        v.x = acc[i][0] + bb; v.y = acc[i][1] + bb;
        v.z = acc[i][2] + bb; v.w = acc[i][3] + bb;
        if (doRelu) {
            v.x = fmaxf(v.x, 0.f); v.y = fmaxf(v.y, 0.f);
            v.z = fmaxf(v.z, 0.f); v.w = fmaxf(v.w, 0.f);
        }
        *(float4*)(C + (size_t)gm * N + n0 + ng * 4) = v;
    }
}

// ---------------- pack head weights ----------------
__global__ void pack_head(const float* __restrict__ Wc, const float* __restrict__ bc,
                          const float* __restrict__ Wb, const float* __restrict__ bb) {
    int idx = blockIdx.x * 256 + threadIdx.x;
    if (idx < HROWS * 512) {
        int row = idx / 512, col = idx % 512;
        g_wh[idx] = (row < 18) ? Wc[row * 512 + col] : Wb[(row - 18) * 512 + col];
    }
    if (idx < HROWS) g_bh[idx] = (idx < 18) ? bc[idx] : bb[idx - 18];
}

// ---------------- emu scores + clear ----------------
__global__ void escore_kernel() {
    int idx = blockIdx.x * 256 + threadIdx.x;
    if (idx < BATCH * POS) g_pflag[idx] = 0;
    if (idx >= BATCH * NPROP) return;
    g_scores[idx] = 0.f;
    int b = idx / NPROP;
    int i = idx - b * NPROP;
    int pos = i / NANCH;
    int a = i - pos * NANCH;
    int n = b * POS + pos;
    float l0 = g_h[(size_t)a * NCOL + n];
    float l1 = g_h[(size_t)(NANCH + a) * NCOL + n];
    float mx = fmaxf(l0, l1);
    float e0 = expf(l0 - mx), e1 = expf(l1 - mx);
    g_escore[idx] = e1 / (e0 + e1);
}

// ---------------- emu cutoff (2048th) ----------------
__global__ __launch_bounds__(1024)
void cutoff_kernel() {
    const int b = blockIdx.x;
    const int tid = threadIdx.x;
    const float* sc = g_escore + (size_t)b * NPROP;
    __shared__ unsigned sh_hist[256];
    __shared__ unsigned sh_prefix;
    __shared__ int sh_need;
    if (tid == 0) { sh_prefix = 0; sh_need = PRE_NMS; }
    __syncthreads();
    for (int p = 3; p >= 0; p--) {
        for (int v = tid; v < 256; v += 1024) sh_hist[v] = 0;
        __syncthreads();
        unsigned pref = sh_prefix;
        unsigned pm = (p == 3) ? 0u : (0xFFFFFFFFu << ((p + 1) * 8));
        for (int i = tid; i < NPROP; i += 1024) {
            unsigned rk = rkey(sc[i]);
            if ((rk & pm) == pref) atomicAdd(&sh_hist[(rk >> (p * 8)) & 255], 1u);
        }
        __syncthreads();
        if (tid == 0) {
            int need = sh_need;
            unsigned acc = 0;
            for (int v = 0; v < 256; v++) {
                unsigned c = sh_hist[v];
                if (need <= (int)(acc + c)) {
                    sh_prefix = pref | ((unsigned)v << (p * 8));
                    sh_need = need - (int)acc;
                    break;
                }
                acc += c;
            }
        }
        __syncthreads();
    }
    if (tid == 0) {
        unsigned m = ~sh_prefix;
        float cf = __uint_as_float(m & 0x7FFFFFFFu);
        g_thr[b] = cf - MARGIN;
    }
}

// ---------------- candidate flags ----------------
__global__ void flag_kernel() {
    int idx = blockIdx.x * 256 + threadIdx.x;
    if (idx >= BATCH * NPROP) return;
    int b = idx / NPROP;
    if (g_escore[idx] >= g_thr[b]) {
        int pos = (idx - b * NPROP) / NANCH;
        g_pflag[b * POS + pos] = 1;
    }
}

// ---------------- compaction ----------------
__global__ __launch_bounds__(1024)
void compact_kernel() {
    __shared__ int warp_sums[32];
    __shared__ int base_off;
    int tid = threadIdx.x;
    int lane = tid & 31, wrp = tid >> 5;
    if (tid == 0) base_off = 0;
    __syncthreads();
    for (int b = 0; b < BATCH; b++) {
        int cnt = 0;
        int mypos[8];
#pragma unroll
        for (int u = 0; u < 8; u++) {
            int pos = tid * 8 + u;
            if (g_pflag[b * POS + pos]) mypos[cnt++] = pos;
        }
        int v = cnt;
#pragma unroll
        for (int o = 1; o < 32; o <<= 1) {
            int t = __shfl_up_sync(0xffffffffu, v, o);
            if (lane >= o) v += t;
        }
        if (lane == 31) warp_sums[wrp] = v;
        __syncthreads();
        if (wrp == 0) {
            int wv = warp_sums[lane];
#pragma unroll
            for (int o = 1; o < 32; o <<= 1) {
                int t = __shfl_up_sync(0xffffffffu, wv, o);
                if (lane >= o) wv += t;
            }
            warp_sums[lane] = wv;
        }
        __syncthreads();
        int excl = v - cnt + (wrp ? warp_sums[wrp - 1] : 0);
        int bo = base_off;
        for (int u = 0; u < cnt; u++) {
            int slot = bo + excl + u;
            if (slot < CCAP) g_plist[slot] = b * POS + mypos[u];
        }
        __syncthreads();
        if (tid == 0) {
            int tot = warp_sums[31];
            int nb = base_off + tot; if (nb > CCAP) nb = CCAP;
            if (b == 0) g_nc[0] = nb;
            base_off = nb;
            if (b == BATCH - 1) {
                g_nc[1] = base_off;
                g_nc[2] = (base_off + 63) & ~63;
            }
        }
        __syncthreads();
    }
}

// ---------------- gather (coalesced writes) ----------------
__global__ void gather_kernel(const float* __restrict__ bf) {
    int j0 = blockIdx.x * 32;
    if (j0 >= g_nc[1]) return;
    int jl = threadIdx.x & 31;
    int kl = threadIdx.x >> 5;
    int j = j0 + jl;
    int n = g_plist[j];
    int b = n >> 13, pos = n & (POS - 1);
#pragma unroll
    for (int kk = 0; kk < 16; kk++) {
        int k = blockIdx.y * 128 + kl * 16 + kk;
        g_colc[(size_t)k * CW + j] = im2col_val(bf, b, pos, k);
    }
}

// ---------------- exact decode for candidates ----------------
__global__ void decode_cand_kernel(const float* __restrict__ im_info) {
    int idx = blockIdx.x * 256 + threadIdx.x;
    int cidx = idx / NANCH;
    if (cidx >= g_nc[1]) return;
    int a = idx - cidx * NANCH;
    int n = g_plist[cidx];
    int b = n >> 13, pos = n & (POS - 1);
    int i = pos * NANCH + a;

    float l0 = g_hc[(size_t)a * CW + cidx];
    float l1 = g_hc[(size_t)(NANCH + a) * CW + cidx];
    float mx = fmaxf(l0, l1);
    float e0 = expf(l0 - mx), e1 = expf(l1 - mx);
    g_scores[(size_t)b * NPROP + i] = e1 / (e0 + e1);

    const float* hd = g_hc + (size_t)(18 + a * 6) * CW + cidx;
    float dx = hd[0 * (size_t)CW], dy = hd[1 * (size_t)CW], dz = hd[2 * (size_t)CW];
    float dw = hd[3 * (size_t)CW], dh = hd[4 * (size_t)CW], dd = hd[5 * (size_t)CW];

    int wp = pos & 31, hp = (pos >> 5) & 31, dp = pos >> 10;
    float s = 4.f * (float)(1 << (a % 3));
    float r = 0.5f * (float)(1 << (a / 3));
    float wsz = 8.f * s;
    float dsz = 8.f * s * r;
    const float ctr = 3.5f;
    float sx = wp * 8.f, sy = hp * 8.f, sz = dp * 8.f;

    float x1 = sx + ctr - 0.5f * (wsz - 1.f), x2 = sx + ctr + 0.5f * (wsz - 1.f);
    float y1 = sy + ctr - 0.5f * (wsz - 1.f), y2 = sy + ctr + 0.5f * (wsz - 1.f);
    float z1 = sz + ctr - 0.5f * (dsz - 1.f), z2 = sz + ctr + 0.5f * (dsz - 1.f);

    float aw = x2 - x1 + 1.f, ah = y2 - y1 + 1.f, ad = z2 - z1 + 1.f;
    float cx = x1 + 0.5f * aw, cy = y1 + 0.5f * ah, cz = z1 + 0.5f * ad;

    float pcx = dx * aw + cx, pcy = dy * ah + cy, pcz = dz * ad + cz;
    float pw = expf(dw) * aw, ph = expf(dh) * ah, pd = expf(dd) * ad;

    float ox1 = pcx - 0.5f * pw, oy1 = pcy - 0.5f * ph, oz1 = pcz - 0.5f * pd;
    float ox2 = pcx + 0.5f * pw, oy2 = pcy + 0.5f * ph, oz2 = pcz + 0.5f * pd;

    float hix = im_info[b * 3 + 2] - 1.f;
    float hiy = im_info[b * 3 + 1] - 1.f;
    float hiz = im_info[b * 3 + 0] - 1.f;
    ox1 = fminf(fmaxf(ox1, 0.f), hix); ox2 = fminf(fmaxf(ox2, 0.f), hix);
    oy1 = fminf(fmaxf(oy1, 0.f), hiy); oy2 = fminf(fmaxf(oy2, 0.f), hiy);
    oz1 = fminf(fmaxf(oz1, 0.f), hiz); oz2 = fminf(fmaxf(oz2, 0.f), hiz);

    float* ob = g_boxes + ((size_t)b * NPROP + i) * 6;
    ob[0] = ox1; ob[1] = oy1; ob[2] = oz1; ob[3] = ox2; ob[4] = oy2; ob[5] = oz2;
}

// ---------------- top-2048 select (exact jax top_k order) ----------------
__global__ __launch_bounds__(1024)
void select_topk_kernel() {
    const int b = blockIdx.x;
    const int tid = threadIdx.x;
    const float* sc = g_scores + (size_t)b * NPROP;

    __shared__ unsigned sh_hist[256];
    __shared__ unsigned sh_prefix;
    __shared__ int sh_need;
    __shared__ int sh_cnt;
    __shared__ unsigned long long s[4096];

    if (tid == 0) { sh_prefix = 0; sh_need = PRE_NMS; }
    __syncthreads();

    for (int p = 3; p >= 0; p--) {
        for (int v = tid; v < 256; v += 1024) sh_hist[v] = 0;
        __syncthreads();
        unsigned pref = sh_prefix;
        unsigned pm = (p == 3) ? 0u : (0xFFFFFFFFu << ((p + 1) * 8));
        for (int i = tid; i < NPROP; i += 1024) {
            unsigned rk = rkey(sc[i]);
            if ((rk & pm) == pref) atomicAdd(&sh_hist[(rk >> (p * 8)) & 255], 1u);
        }
        __syncthreads();
        if (tid == 0) {
            int need = sh_need;
            unsigned acc = 0;
            for (int v = 0; v < 256; v++) {
                unsigned c = sh_hist[v];
                if (need <= (int)(acc + c)) {
                    sh_prefix = pref | ((unsigned)v << (p * 8));
                    sh_need = need - (int)acc;
                    break;
                }
                acc += c;
            }
        }
        __syncthreads();
    }
    unsigned cutoff = sh_prefix;
    if (tid == 0) sh_cnt = 0;
    __syncthreads();

    for (int i = tid; i < NPROP; i += 1024) {
        unsigned rk = rkey(sc[i]);
        if (rk <= cutoff) {
            int posn = atomicAdd(&sh_cnt, 1);
            if (posn < 4096)
                g_cand[b][posn] = ((unsigned long long)rk << 32) | (unsigned)i;
        }
    }
    __syncthreads();
    int total = sh_cnt; if (total > 4096) total = 4096;
    for (int i = tid; i < 4096; i += 1024)
        s[i] = (i < total) ? g_cand[b][i] : 0xFFFFFFFFFFFFFFFFull;
    __syncthreads();

    for (int k = 2; k <= 4096; k <<= 1) {
        for (int j = k >> 1; j > 0; j >>= 1) {
            for (int i = tid; i < 4096; i += 1024) {
                int l = i ^ j;
                if (l > i) {
                    unsigned long long a = s[i], c = s[l];
                    bool sw = ((i & k) == 0) ? (a > c) : (a < c);
                    if (sw) { s[i] = c; s[l] = a; }
                }
            }
            __syncthreads();
        }
    }

    for (int r2 = tid; r2 < PRE_NMS; r2 += 1024) {
        unsigned idx = (unsigned)(s[r2] & 0xFFFFFFFFull);
        const float* src = g_boxes + ((size_t)b * NPROP + idx) * 6;
        float* dst = g_sboxes + ((size_t)b * PRE_NMS + r2) * 6;
#pragma unroll
        for (int c = 0; c < 6; c++) dst[c] = src[c];
    }
}

// ---------------- NMS bitmask ----------------
__global__ void nms_mask_kernel() {
    int b = blockIdx.z, jb = blockIdx.x, ib = blockIdx.y, t = threadIdx.x;
    __shared__ float cb[64][6];
    const float* sb = g_sboxes + (size_t)b * PRE_NMS * 6;
    {
        const float* p = sb + (size_t)(jb * 64 + t) * 6;
#pragma unroll
        for (int c = 0; c < 6; c++) cb[t][c] = p[c];
    }
    __syncthreads();

    int i = ib * 64 + t;
    const float* p = sb + (size_t)i * 6;
    float x1 = p[0], y1 = p[1], z1 = p[2], x2 = p[3], y2 = p[4], z2 = p[5];
    float vi = (x2 - x1 + 1.f) * (y2 - y1 + 1.f) * (z2 - z1 + 1.f);
    unsigned long long bits = 0ull;
#pragma unroll 4
    for (int jj = 0; jj < 64; jj++) {
        float ix = fmaxf(fminf(x2, cb[jj][3]) - fmaxf(x1, cb[jj][0]) + 1.f, 0.f);
        float iy = fmaxf(fminf(y2, cb[jj][4]) - fmaxf(y1, cb[jj][1]) + 1.f, 0.f);
        float iz = fmaxf(fminf(z2, cb[jj][5]) - fmaxf(z1, cb[jj][2]) + 1.f, 0.f);
        float inter = ix * iy * iz;
        float vj = (cb[jj][3] - cb[jj][0] + 1.f) * (cb[jj][4] - cb[jj][1] + 1.f)
                 * (cb[jj][5] - cb[jj][2] + 1.f);
        float iou = inter / (vi + vj - inter);
        if (iou > NMS_TH) bits |= (1ull << jj);
    }
    g_mask[((size_t)b * PRE_NMS + i) * 32 + jb] = bits;
}

// ---------------- sequential keep-scan + output (16-deep prefetch ring) ----------------
__global__ void nms_scan_kernel(float* __restrict__ out) {
    int b = blockIdx.x;
    int lane = threadIdx.x;
    __shared__ unsigned short keep[POST_NMS];
    unsigned long long rem = 0ull;
    int nk = 0;
    const unsigned long long* mb = g_mask + (size_t)b * PRE_NMS * 32;

    unsigned long long pf[16];
#pragma unroll
    for (int u = 0; u < 16; u++) pf[u] = mb[(size_t)u * 32 + lane];

    for (int base = 0; base < PRE_NMS; base += 16) {
#pragma unroll
        for (int u = 0; u < 16; u++) {
            int i = base + u;
            unsigned long long w = __shfl_sync(0xffffffffu, rem, i >> 6);
            unsigned long long m = pf[u];
            int nx = i + 16;
            if (nx < PRE_NMS) pf[u] = mb[(size_t)nx * 32 + lane];
            if (!((w >> (i & 63)) & 1ull)) {
                if (lane == 0 && nk < POST_NMS) keep[nk] = (unsigned short)i;
                nk++;
                rem |= m;
            }
        }
    }
    __syncwarp();
    for (int r = lane; r < POST_NMS; r += 32) {
        float* o = out + ((size_t)b * POST_NMS + r) * 7;
        o[0] = (float)b;
        if (r < nk) {
            int i = keep[r];
            const float* bx = g_sboxes + ((size_t)b * PRE_NMS + i) * 6;
#pragma unroll
            for (int c = 0; c < 6; c++) o[1 + c] = bx[c];
        } else {
#pragma unroll
            for (int c = 0; c < 6; c++) o[1 + c] = 0.f;
        }
    }
}

// ---------------- launch ----------------
extern "C" void kernel_launch(void* const* d_in, const int* in_sizes, int n_in,
                              void* d_out, int out_size) {
    const float* base_feat = (const float*)d_in[0];
    const float* im_info   = (const float*)d_in[1];
    const float* W_conv    = (const float*)d_in[4];
    const float* b_conv    = (const float*)d_in[5];
    const float* W_cls     = (const float*)d_in[6];
    const float* b_cls     = (const float*)d_in[7];
    const float* W_bbox    = (const float*)d_in[8];
    const float* b_bbox    = (const float*)d_in[9];
    float* out = (float*)d_out;

    float *p_wh, *p_bh, *p_colc, *p_xc, *p_hc;
    int* p_nc;
    cudaGetSymbolAddress((void**)&p_wh,   g_wh);
    cudaGetSymbolAddress((void**)&p_bh,   g_bh);
    cudaGetSymbolAddress((void**)&p_colc, g_colc);
    cudaGetSymbolAddress((void**)&p_xc,   g_xc);
    cudaGetSymbolAddress((void**)&p_hc,   g_hc);
    cudaGetSymbolAddress((void**)&p_nc,   g_nc);

    cudaFuncSetAttribute(conv_emu_kernel, cudaFuncAttributeMaxDynamicSharedMemorySize, SMEM_EMU);

    zero_fp_kernel<<<(int)((FPAD / 8 + 255) / 256), 256>>>();
    tsplit_kernel<<<BATCH * DD * HH, 256>>>(base_feat);
    a_reord_kernel<<<(COUT * KDIM + 255) / 256, 256>>>(W_conv);
    {   // emu conv (implicit im2col, single-bf16 term)
        dim3 grid(COUT / 128, NCOL / 128);
        conv_emu_kernel<<<grid, 256, SMEM_EMU>>>(b_conv);
    }
    pack_head<<<(HROWS * 512 + 255) / 256, 256>>>(W_cls, b_cls, W_bbox, b_bbox);
    head18_kernel<<<NCOL / 128, 128>>>();
    escore_kernel<<<(BATCH * NPROP + 255) / 256, 256>>>();
    cutoff_kernel<<<BATCH, 1024>>>();
    flag_kernel<<<(BATCH * NPROP + 255) / 256, 256>>>();
    compact_kernel<<<1, 1024>>>();
    {
        dim3 grid(CCAP / 32, 27);
        gather_kernel<<<grid, 256>>>(base_feat);
    }
    {   // exact conv on compacted columns (32x64 tiles, R1-identical numerics)
        dim3 grid(CW / 64, COUT / 32);
        exact32x64<<<grid, 128>>>(W_conv, p_colc, p_xc, b_conv, COUT, CW, KDIM, 1, p_nc + 2);
    }
    {   // exact heads on compacted columns
        dim3 grid(CW / 64, (HROWS + 31) / 32);
        exact32x64<<<grid, 128>>>(p_wh, p_xc, p_hc, p_bh, HROWS, CW, 512, 0, p_nc + 2);
    }
    decode_cand_kernel<<<(CCAP * NANCH + 255) / 256, 256>>>(im_info);
    select_topk_kernel<<<BATCH, 1024>>>();
    {
        dim3 grid(PRE_NMS / 64, PRE_NMS / 64, BATCH);
        nms_mask_kernel<<<grid, 64>>>();
    }
    nms_scan_kernel<<<BATCH, 32>>>(out);
}

// round 16
// speedup vs baseline: 1.1828x; 1.0059x over previous
#include <cuda_runtime.h>
#include <cuda_bf16.h>
#include <math.h>
#include <stdint.h>

// ---------------- problem constants ----------------
#define BATCH   2
#define CIN     128
#define COUT    512
#define DD      8
#define HH      32
#define WW      32
#define POS     (DD*HH*WW)          // 8192
#define NCOL    (BATCH*POS)         // 16384
#define KDIM    (CIN*27)            // 3456
#define NANCH   9
#define NPROP   (POS*NANCH)         // 73728 per batch
#define PRE_NMS 2048
#define POST_NMS 300
#define NMS_TH  0.7f
#define HROWS   72
#define CLSROWS 18
#define MARGIN  4e-3f
#define CCAP    8192
#define CW      8192

// emu conv tiling (A bf16 x B bf16, single term), K reordered as (off, c)
#define TILE_K    32
#define KITERS    (KDIM/TILE_K)     // 108
#define PLANE_W   (128*20)
#define STAGE_W   (2*PLANE_W)       // A, B1
#define STAGE_B   (STAGE_W*4)       // 20480 bytes
#define NSTG      5
#define SMEM_EMU  (NSTG*STAGE_B)    // 102400

// padded transposed feature map: [B][D+2][H+2][W+2][C]
#define FPD     (DD+2)
#define FPH     (HH+2)
#define FPW     (WW+2)
#define FPAD    ((size_t)BATCH*FPD*FPH*FPW*CIN)

// ---------------- static scratch ----------------
__device__ __align__(128) __nv_bfloat16 g_fp1[FPAD];
__device__ __align__(128) __nv_bfloat16 g_ar [(size_t)COUT * KDIM];
__device__ float g_xe  [(size_t)COUT * NCOL];
__device__ float g_h   [(size_t)CLSROWS * NCOL];
__device__ float g_colc[(size_t)KDIM * CW];
__device__ float g_xc  [(size_t)COUT * CW];
__device__ float g_hc  [(size_t)HROWS * CW];
__device__ float g_wh  [HROWS * 512];
__device__ float g_bh  [HROWS];
__device__ float g_escore[BATCH * NPROP];
__device__ float g_thr[BATCH];
__device__ int   g_pflag[BATCH * POS];
__device__ int   g_plist[CCAP];
__device__ int   g_nc[4];
__device__ float g_scores[BATCH * NPROP];
__device__ float g_boxes [(size_t)BATCH * NPROP * 6];
__device__ unsigned long long g_cand[BATCH][4096];
__device__ float g_sboxes[(size_t)BATCH * PRE_NMS * 6];
__device__ unsigned long long g_mask[(size_t)BATCH * PRE_NMS * 32];

// ---------------- helpers ----------------
__device__ __forceinline__ uint32_t smem_u32(const void* p) {
    uint32_t a;
    asm("{ .reg .u64 t; cvta.to.shared.u64 t, %1; cvt.u32.u64 %0, t; }" : "=r"(a) : "l"(p));
    return a;
}
__device__ __forceinline__ void cp_async16(uint32_t dst, const void* src) {
    asm volatile("cp.async.cg.shared.global [%0], [%1], 16;" :: "r"(dst), "l"(src));
}
__device__ __forceinline__ void cp_commit() { asm volatile("cp.async.commit_group;" ::: "memory"); }
__device__ __forceinline__ void cp_wait4()  { asm volatile("cp.async.wait_group 4;" ::: "memory"); }
__device__ __forceinline__ void cp_wait3()  { asm volatile("cp.async.wait_group 3;" ::: "memory"); }
__device__ __forceinline__ void cp_wait2()  { asm volatile("cp.async.wait_group 2;" ::: "memory"); }
__device__ __forceinline__ void cp_wait1()  { asm volatile("cp.async.wait_group 1;" ::: "memory"); }
__device__ __forceinline__ void cp_wait0()  { asm volatile("cp.async.wait_group 0;" ::: "memory"); }

__device__ __forceinline__ void mma_bf16(float c[4], const uint32_t a[4], const uint32_t b[2]) {
    asm volatile("mma.sync.aligned.m16n8k16.row.col.f32.bf16.bf16.f32 "
        "{%0,%1,%2,%3}, {%4,%5,%6,%7}, {%8,%9}, {%0,%1,%2,%3};"
        : "+f"(c[0]), "+f"(c[1]), "+f"(c[2]), "+f"(c[3])
        : "r"(a[0]), "r"(a[1]), "r"(a[2]), "r"(a[3]), "r"(b[0]), "r"(b[1]));
}
__device__ __forceinline__ unsigned int rkey(float f) {
    unsigned u = __float_as_uint(f);
    u = (u & 0x80000000u) ? ~u : (u | 0x80000000u);
    return ~u;
}

// ---------------- im2col value (exact path; original K order c*27+off) ----------------
__device__ __forceinline__ float im2col_val(const float* __restrict__ bf, int b, int pos, int k) {
    int c = k / 27; int rem = k - c * 27;
    int kd = rem / 9, kh = (rem % 9) / 3, kw = rem % 3;
    int d = pos >> 10, h = (pos >> 5) & 31, w = pos & 31;
    int zd = d + kd - 1, zh = h + kh - 1, zw = w + kw - 1;
    if ((unsigned)zd < DD && (unsigned)zh < HH && (unsigned)zw < WW)
        return bf[(((size_t)(b * CIN + c) * DD + zd) * HH + zh) * WW + zw];
    return 0.f;
}

// ---------------- zero padded feature map ----------------
__global__ void zero_fp_kernel() {
    size_t idx = (size_t)(blockIdx.x * 256 + threadIdx.x) * 8;
    if (idx < FPAD)
        *(uint4*)(g_fp1 + idx) = make_uint4(0, 0, 0, 0);
}

// ---------------- transpose + bf16 round ----------------
__global__ void tsplit_kernel(const float* __restrict__ bf) {
    __shared__ float tile[128][33];
    int blk = blockIdx.x;
    int b = blk >> 8;
    int d = (blk >> 5) & 7;
    int h = blk & 31;
    int t = threadIdx.x;

    int w = t & 31, cr = t >> 5;
#pragma unroll
    for (int i = 0; i < 16; i++) {
        int c = i * 8 + cr;
        tile[c][w] = bf[(((size_t)(b * CIN + c) * DD + d) << 10) + h * 32 + w];
    }
    __syncthreads();

    int c2 = t & 127, wr = t >> 7;
    size_t obase = ((((size_t)b * FPD + d + 1) * FPH + h + 1) * FPW + 1) * 128;
#pragma unroll
    for (int i = 0; i < 16; i++) {
        int w2 = i * 2 + wr;
        g_fp1[obase + (size_t)w2 * 128 + c2] = __float2bfloat16_rn(tile[c2][w2]);
    }
}

// ---------------- weight reorder to k=(off, c), bf16 ----------------
__global__ void a_reord_kernel(const float* __restrict__ Wc) {
    int idx = blockIdx.x * 256 + threadIdx.x;
    if (idx >= COUT * KDIM) return;
    int m = idx / KDIM, k = idx - m * KDIM;
    int off = k >> 7, c = k & 127;
    g_ar[idx] = __float2bfloat16_rn(Wc[(size_t)m * KDIM + c * 27 + off]);
}

// ---------------- emu conv: implicit im2col, A bf16 x B bf16 ----------------
__device__ __forceinline__ void load_stage_emu(uint32_t sbase, int it, int m0,
                                               int bb, int dd, int h0, int tid) {
    int k0 = it * TILE_K;
    int off = k0 >> 7;
    int c0  = k0 & 127;
    int kd = off / 9; int r9 = off - kd * 9;
    int kh = r9 / 3;  int kw = r9 - kh * 3;

#pragma unroll
    for (int i = 0; i < 2; i++) {
        int cwp = i * 256 + tid;
        int row = cwp >> 2, quad = cwp & 3;
        uint32_t doff = (uint32_t)(row * 80 + quad * 16);
        cp_async16(sbase + doff, g_ar + (size_t)(m0 + row) * KDIM + k0 + quad * 8);
    }
#pragma unroll
    for (int i = 0; i < 2; i++) {
        int cwp = i * 256 + tid;
        int row = cwp >> 2, quad = cwp & 3;
        int h = h0 + (row >> 5);
        int w = row & 31;
        size_t base = ((((size_t)bb * FPD + dd + kd) * FPH + h + kh) * FPW + (w + kw)) * 128
                    + c0 + quad * 8;
        uint32_t doff = (uint32_t)(PLANE_W * 4 + row * 80 + quad * 16);
        cp_async16(sbase + doff, g_fp1 + base);
    }
    cp_commit();
}

__global__ __launch_bounds__(256)
void conv_emu_kernel(const float* __restrict__ bias) {
    extern __shared__ __align__(16) uint32_t smem[];
    const int tid  = threadIdx.x;
    const int wid  = tid >> 5;
    const int lane = tid & 31;
    const int m0 = blockIdx.x * 128;
    const int n0 = blockIdx.y * 128;
    const int m_off = (wid >> 1) * 32;
    const int n_off = (wid & 1) * 64;
    const int qr = lane >> 2, qc = lane & 3;
    uint32_t sb = smem_u32(smem);

    const int bb = n0 >> 13;
    const int pos0 = n0 & (POS - 1);
    const int dd = pos0 >> 10;
    const int h0 = (pos0 >> 5) & 31;

    float acc[2][8][4];
#pragma unroll
    for (int i = 0; i < 2; i++)
#pragma unroll
        for (int j = 0; j < 8; j++)
#pragma unroll
            for (int t = 0; t < 4; t++) acc[i][j][t] = 0.f;

#pragma unroll
    for (int s = 0; s < NSTG; s++)
        load_stage_emu(sb + s * STAGE_B, s, m0, bb, dd, h0, tid);

    for (int it = 0; it < KITERS; it++) {
        if (it < KITERS - 4) cp_wait4();
        else if (it < KITERS - 3) cp_wait3();
        else if (it < KITERS - 2) cp_wait2();
        else if (it < KITERS - 1) cp_wait1();
        else cp_wait0();
        __syncthreads();

        const uint32_t* S = smem + (it % NSTG) * STAGE_W;
        const uint32_t* A1 = S;
        const uint32_t* B1 = S + PLANE_W;

#pragma unroll
        for (int q = 0; q < 2; q++) {
            int w0 = q * 8 + qc;
            uint32_t a1[2][4];
#pragma unroll
            for (int i = 0; i < 2; i++) {
                int r = m_off + i * 16 + qr;
                a1[i][0] = A1[r * 20 + w0];       a1[i][1] = A1[(r + 8) * 20 + w0];
                a1[i][2] = A1[r * 20 + w0 + 4];   a1[i][3] = A1[(r + 8) * 20 + w0 + 4];
            }
#pragma unroll
            for (int j = 0; j < 8; j++) {
                int n = n_off + j * 8 + qr;
                uint32_t b1[2] = { B1[n * 20 + w0], B1[n * 20 + w0 + 4] };
#pragma unroll
                for (int i = 0; i < 2; i++)
                    mma_bf16(acc[i][j], a1[i], b1);
            }
        }
        __syncthreads();
        if (it + NSTG < KITERS)
            load_stage_emu(sb + ((it + NSTG) % NSTG) * STAGE_B, it + NSTG, m0, bb, dd, h0, tid);
    }

#pragma unroll
    for (int i = 0; i < 2; i++) {
        int r0 = m0 + m_off + i * 16 + qr;
        float b0 = bias[r0], b1v = bias[r0 + 8];
#pragma unroll
        for (int j = 0; j < 8; j++) {
            int c0 = n0 + n_off + j * 8 + qc * 2;
            float2 v0, v1;
            v0.x = fmaxf(acc[i][j][0] + b0, 0.f);
            v0.y = fmaxf(acc[i][j][1] + b0, 0.f);
            v1.x = fmaxf(acc[i][j][2] + b1v, 0.f);
            v1.y = fmaxf(acc[i][j][3] + b1v, 0.f);
            *(float2*)(g_xe + (size_t)r0 * NCOL + c0) = v0;
            *(float2*)(g_xe + (size_t)(r0 + 8) * NCOL + c0) = v1;
        }
    }
}

// ---------------- emu heads: 18 cls rows, dedicated kernel ----------------
__global__ __launch_bounds__(128)
void head18_kernel() {
    __shared__ float w[CLSROWS * 512];
    int t = threadIdx.x;
    for (int i = t; i < CLSROWS * 512; i += 128) w[i] = g_wh[i];
    __syncthreads();
    int n = blockIdx.x * 128 + t;
    float acc[CLSROWS];
#pragma unroll
    for (int r = 0; r < CLSROWS; r++) acc[r] = g_bh[r];
    for (int k = 0; k < 512; k++) {
        float xv = g_xe[(size_t)k * NCOL + n];
#pragma unroll
        for (int r = 0; r < CLSROWS; r++) acc[r] = fmaf(w[r * 512 + k], xv, acc[r]);
    }
#pragma unroll
    for (int r = 0; r < CLSROWS; r++) g_h[(size_t)r * NCOL + n] = acc[r];
}

// ---------------- exact GEMM, 32m x 64n tiles (bit-identical k-ascending fmaf chains) ----------------
__global__ __launch_bounds__(128)
void exact32x64(const float* __restrict__ A, const float* __restrict__ B,
                float* __restrict__ C, const float* __restrict__ bias,
                int M, int N, int K, int doRelu, const int* __restrict__ nlim) {
    if (blockIdx.x * 64 >= *nlim) return;
    __shared__ float As[2][8][32];
    __shared__ float Bs[2][8][64];
    const int tid = threadIdx.x;
    const int m0 = blockIdx.y * 32;
    const int n0 = blockIdx.x * 64;
    const int mg = tid >> 4, ng = tid & 15;
    const int am = tid & 31, akq = (tid >> 5) * 4;
    const int bk = tid >> 4, bn4 = (tid & 15) * 4;

    float acc[4][4];
#pragma unroll
    for (int i = 0; i < 4; i++)
#pragma unroll
        for (int j = 0; j < 4; j++) acc[i][j] = 0.f;

    float4 av = make_float4(0.f, 0.f, 0.f, 0.f), bv;
    {
        if (tid < 64) {
            int gm = m0 + am;
            if (gm < M) av = *(const float4*)(A + (size_t)gm * K + akq);
        }
        bv = *(const float4*)(B + (size_t)bk * N + n0 + bn4);
        if (tid < 64) {
            As[0][akq + 0][am] = av.x; As[0][akq + 1][am] = av.y;
            As[0][akq + 2][am] = av.z; As[0][akq + 3][am] = av.w;
        }
        *(float4*)&Bs[0][bk][bn4] = bv;
    }
    __syncthreads();

    int cur = 0;
    for (int kt = 8; kt < K; kt += 8) {
        av = make_float4(0.f, 0.f, 0.f, 0.f);
        if (tid < 64) {
            int gm = m0 + am;
            if (gm < M) av = *(const float4*)(A + (size_t)gm * K + kt + akq);
        }
        bv = *(const float4*)(B + (size_t)(kt + bk) * N + n0 + bn4);

#pragma unroll
        for (int kk = 0; kk < 8; kk++) {
            float4 a = *(const float4*)&As[cur][kk][mg * 4];
            float4 b = *(const float4*)&Bs[cur][kk][ng * 4];
            acc[0][0] = fmaf(a.x, b.x, acc[0][0]); acc[0][1] = fmaf(a.x, b.y, acc[0][1]);
            acc[0][2] = fmaf(a.x, b.z, acc[0][2]); acc[0][3] = fmaf(a.x, b.w, acc[0][3]);
            acc[1][0] = fmaf(a.y, b.x, acc[1][0]); acc[1][1] = fmaf(a.y, b.y, acc[1][1]);
            acc[1][2] = fmaf(a.y, b.z, acc[1][2]); acc[1][3] = fmaf(a.y, b.w, acc[1][3]);
            acc[2][0] = fmaf(a.z, b.x, acc[2][0]); acc[2][1] = fmaf(a.z, b.y, acc[2][1]);
            acc[2][2] = fmaf(a.z, b.z, acc[2][2]); acc[2][3] = fmaf(a.z, b.w, acc[2][3]);
            acc[3][0] = fmaf(a.w, b.x, acc[3][0]); acc[3][1] = fmaf(a.w, b.y, acc[3][1]);
            acc[3][2] = fmaf(a.w, b.z, acc[3][2]); acc[3][3] = fmaf(a.w, b.w, acc[3][3]);
        }
        int nxt = cur ^ 1;
        if (tid < 64) {
            As[nxt][akq + 0][am] = av.x; As[nxt][akq + 1][am] = av.y;
            As[nxt][akq + 2][am] = av.z; As[nxt][akq + 3][am] = av.w;
        }
        *(float4*)&Bs[nxt][bk][bn4] = bv;
        __syncthreads();
        cur = nxt;
    }
#pragma unroll
    for (int kk = 0; kk < 8; kk++) {
        float4 a = *(const float4*)&As[cur][kk][mg * 4];
        float4 b = *(const float4*)&Bs[cur][kk][ng * 4];
        acc[0][0] = fmaf(a.x, b.x, acc[0][0]); acc[0][1] = fmaf(a.x, b.y, acc[0][1]);
        acc[0][2] = fmaf(a.x, b.z, acc[0][2]); acc[0][3] = fmaf(a.x, b.w, acc[0][3]);
        acc[1][0] = fmaf(a.y, b.x, acc[1][0]); acc[1][1] = fmaf(a.y, b.y, acc[1][1]);
        acc[1][2] = fmaf(a.y, b.z, acc[1][2]); acc[1][3] = fmaf(a.y, b.w, acc[1][3]);
        acc[2][0] = fmaf(a.z, b.x, acc[2][0]); acc[2][1] = fmaf(a.z, b.y, acc[2][1]);
        acc[2][2] = fmaf(a.z, b.z, acc[2][2]); acc[2][3] = fmaf(a.z, b.w, acc[2][3]);
        acc[3][0] = fmaf(a.w, b.x, acc[3][0]); acc[3][1] = fmaf(a.w, b.y, acc[3][1]);
        acc[3][2] = fmaf(a.w, b.z, acc[3][2]); acc[3][3] = fmaf(a.w, b.w, acc[3][3]);
    }

#pragma unroll
    for (int i = 0; i < 4; i++) {
        int gm = m0 + mg * 4 + i;
        if (gm >= M) continue;
        float bb = bias[gm];
        float4 v;
        v.x = acc[i][0] + bb; v.y = acc[i][1] + bb;
        v.z = acc[i][2] + bb; v.w = acc[i][3] + bb;
        if (doRelu) {
            v.x = fmaxf(v.x, 0.f); v.y = fmaxf(v.y, 0.f);
            v.z = fmaxf(v.z, 0.f); v.w = fmaxf(v.w, 0.f);
        }
        *(float4*)(C + (size_t)gm * N + n0 + ng * 4) = v;
    }
}

// ---------------- pack head weights ----------------
__global__ void pack_head(const float* __restrict__ Wc, const float* __restrict__ bc,
                          const float* __restrict__ Wb, const float* __restrict__ bb) {
    int idx = blockIdx.x * 256 + threadIdx.x;
    if (idx < HROWS * 512) {
        int row = idx / 512, col = idx % 512;
        g_wh[idx] = (row < 18) ? Wc[row * 512 + col] : Wb[(row - 18) * 512 + col];
    }
    if (idx < HROWS) g_bh[idx] = (idx < 18) ? bc[idx] : bb[idx - 18];
}

// ---------------- emu scores + clear ----------------
__global__ void escore_kernel() {
    int idx = blockIdx.x * 256 + threadIdx.x;
    if (idx < BATCH * POS) g_pflag[idx] = 0;
    if (idx >= BATCH * NPROP) return;
    g_scores[idx] = 0.f;
    int b = idx / NPROP;
    int i = idx - b * NPROP;
    int pos = i / NANCH;
    int a = i - pos * NANCH;
    int n = b * POS + pos;
    float l0 = g_h[(size_t)a * NCOL + n];
    float l1 = g_h[(size_t)(NANCH + a) * NCOL + n];
    float mx = fmaxf(l0, l1);
    float e0 = expf(l0 - mx), e1 = expf(l1 - mx);
    g_escore[idx] = e1 / (e0 + e1);
}

// ---------------- emu cutoff (2048th) ----------------
__global__ __launch_bounds__(1024)
void cutoff_kernel() {
    const int b = blockIdx.x;
    const int tid = threadIdx.x;
    const float* sc = g_escore + (size_t)b * NPROP;
    __shared__ unsigned sh_hist[256];
    __shared__ unsigned sh_prefix;
    __shared__ int sh_need;
    if (tid == 0) { sh_prefix = 0; sh_need = PRE_NMS; }
    __syncthreads();
    for (int p = 3; p >= 0; p--) {
        for (int v = tid; v < 256; v += 1024) sh_hist[v] = 0;
        __syncthreads();
        unsigned pref = sh_prefix;
        unsigned pm = (p == 3) ? 0u : (0xFFFFFFFFu << ((p + 1) * 8));
        for (int i = tid; i < NPROP; i += 1024) {
            unsigned rk = rkey(sc[i]);
            if ((rk & pm) == pref) atomicAdd(&sh_hist[(rk >> (p * 8)) & 255], 1u);
        }
        __syncthreads();
        if (tid == 0) {
            int need = sh_need;
            unsigned acc = 0;
            for (int v = 0; v < 256; v++) {
                unsigned c = sh_hist[v];
                if (need <= (int)(acc + c)) {
                    sh_prefix = pref | ((unsigned)v << (p * 8));
                    sh_need = need - (int)acc;
                    break;
                }
                acc += c;
            }
        }
        __syncthreads();
    }
    if (tid == 0) {
        unsigned m = ~sh_prefix;
        float cf = __uint_as_float(m & 0x7FFFFFFFu);
        g_thr[b] = cf - MARGIN;
    }
}

// ---------------- candidate flags ----------------
__global__ void flag_kernel() {
    int idx = blockIdx.x * 256 + threadIdx.x;
    if (idx >= BATCH * NPROP) return;
    int b = idx / NPROP;
    if (g_escore[idx] >= g_thr[b]) {
        int pos = (idx - b * NPROP) / NANCH;
        g_pflag[b * POS + pos] = 1;
    }
}

// ---------------- compaction ----------------
__global__ __launch_bounds__(1024)
void compact_kernel() {
    __shared__ int warp_sums[32];
    __shared__ int base_off;
    int tid = threadIdx.x;
    int lane = tid & 31, wrp = tid >> 5;
    if (tid == 0) base_off = 0;
    __syncthreads();
    for (int b = 0; b < BATCH; b++) {
        int cnt = 0;
        int mypos[8];
#pragma unroll
        for (int u = 0; u < 8; u++) {
            int pos = tid * 8 + u;
            if (g_pflag[b * POS + pos]) mypos[cnt++] = pos;
        }
        int v = cnt;
#pragma unroll
        for (int o = 1; o < 32; o <<= 1) {
            int t = __shfl_up_sync(0xffffffffu, v, o);
            if (lane >= o) v += t;
        }
        if (lane == 31) warp_sums[wrp] = v;
        __syncthreads();
        if (wrp == 0) {
            int wv = warp_sums[lane];
#pragma unroll
            for (int o = 1; o < 32; o <<= 1) {
                int t = __shfl_up_sync(0xffffffffu, wv, o);
                if (lane >= o) wv += t;
            }
            warp_sums[lane] = wv;
        }
        __syncthreads();
        int excl = v - cnt + (wrp ? warp_sums[wrp - 1] : 0);
        int bo = base_off;
        for (int u = 0; u < cnt; u++) {
            int slot = bo + excl + u;
            if (slot < CCAP) g_plist[slot] = b * POS + mypos[u];
        }
        __syncthreads();
        if (tid == 0) {
            int tot = warp_sums[31];
            int nb = base_off + tot; if (nb > CCAP) nb = CCAP;
            if (b == 0) g_nc[0] = nb;
            base_off = nb;
            if (b == BATCH - 1) {
                g_nc[1] = base_off;
                g_nc[2] = (base_off + 63) & ~63;
            }
        }
        __syncthreads();
    }
}

// ---------------- gather (coalesced writes) ----------------
__global__ void gather_kernel(const float* __restrict__ bf) {
    int j0 = blockIdx.x * 32;
    if (j0 >= g_nc[1]) return;
    int jl = threadIdx.x & 31;
    int kl = threadIdx.x >> 5;
    int j = j0 + jl;
    int n = g_plist[j];
    int b = n >> 13, pos = n & (POS - 1);
#pragma unroll
    for (int kk = 0; kk < 16; kk++) {
        int k = blockIdx.y * 128 + kl * 16 + kk;
        g_colc[(size_t)k * CW + j] = im2col_val(bf, b, pos, k);
    }
}

// ---------------- exact decode for candidates ----------------
__global__ void decode_cand_kernel(const float* __restrict__ im_info) {
    int idx = blockIdx.x * 256 + threadIdx.x;
    int cidx = idx / NANCH;
    if (cidx >= g_nc[1]) return;
    int a = idx - cidx * NANCH;
    int n = g_plist[cidx];
    int b = n >> 13, pos = n & (POS - 1);
    int i = pos * NANCH + a;

    float l0 = g_hc[(size_t)a * CW + cidx];
    float l1 = g_hc[(size_t)(NANCH + a) * CW + cidx];
    float mx = fmaxf(l0, l1);
    float e0 = expf(l0 - mx), e1 = expf(l1 - mx);
    g_scores[(size_t)b * NPROP + i] = e1 / (e0 + e1);

    const float* hd = g_hc + (size_t)(18 + a * 6) * CW + cidx;
    float dx = hd[0 * (size_t)CW], dy = hd[1 * (size_t)CW], dz = hd[2 * (size_t)CW];
    float dw = hd[3 * (size_t)CW], dh = hd[4 * (size_t)CW], dd = hd[5 * (size_t)CW];

    int wp = pos & 31, hp = (pos >> 5) & 31, dp = pos >> 10;
    float s = 4.f * (float)(1 << (a % 3));
    float r = 0.5f * (float)(1 << (a / 3));
    float wsz = 8.f * s;
    float dsz = 8.f * s * r;
    const float ctr = 3.5f;
    float sx = wp * 8.f, sy = hp * 8.f, sz = dp * 8.f;

    float x1 = sx + ctr - 0.5f * (wsz - 1.f), x2 = sx + ctr + 0.5f * (wsz - 1.f);
    float y1 = sy + ctr - 0.5f * (wsz - 1.f), y2 = sy + ctr + 0.5f * (wsz - 1.f);
    float z1 = sz + ctr - 0.5f * (dsz - 1.f), z2 = sz + ctr + 0.5f * (dsz - 1.f);

    float aw = x2 - x1 + 1.f, ah = y2 - y1 + 1.f, ad = z2 - z1 + 1.f;
    float cx = x1 + 0.5f * aw, cy = y1 + 0.5f * ah, cz = z1 + 0.5f * ad;

    float pcx = dx * aw + cx, pcy = dy * ah + cy, pcz = dz * ad + cz;
    float pw = expf(dw) * aw, ph = expf(dh) * ah, pd = expf(dd) * ad;

    float ox1 = pcx - 0.5f * pw, oy1 = pcy - 0.5f * ph, oz1 = pcz - 0.5f * pd;
    float ox2 = pcx + 0.5f * pw, oy2 = pcy + 0.5f * ph, oz2 = pcz + 0.5f * pd;

    float hix = im_info[b * 3 + 2] - 1.f;
    float hiy = im_info[b * 3 + 1] - 1.f;
    float hiz = im_info[b * 3 + 0] - 1.f;
    ox1 = fminf(fmaxf(ox1, 0.f), hix); ox2 = fminf(fmaxf(ox2, 0.f), hix);
    oy1 = fminf(fmaxf(oy1, 0.f), hiy); oy2 = fminf(fmaxf(oy2, 0.f), hiy);
    oz1 = fminf(fmaxf(oz1, 0.f), hiz); oz2 = fminf(fmaxf(oz2, 0.f), hiz);

    float* ob = g_boxes + ((size_t)b * NPROP + i) * 6;
    ob[0] = ox1; ob[1] = oy1; ob[2] = oz1; ob[3] = ox2; ob[4] = oy2; ob[5] = oz2;
}

// ---------------- top-2048 select (exact jax top_k order) ----------------
__global__ __launch_bounds__(1024)
void select_topk_kernel() {
    const int b = blockIdx.x;
    const int tid = threadIdx.x;
    const float* sc = g_scores + (size_t)b * NPROP;

    __shared__ unsigned sh_hist[256];
    __shared__ unsigned sh_prefix;
    __shared__ int sh_need;
    __shared__ int sh_cnt;
    __shared__ unsigned long long s[4096];

    if (tid == 0) { sh_prefix = 0; sh_need = PRE_NMS; }
    __syncthreads();

    for (int p = 3; p >= 0; p--) {
        for (int v = tid; v < 256; v += 1024) sh_hist[v] = 0;
        __syncthreads();
        unsigned pref = sh_prefix;
        unsigned pm = (p == 3) ? 0u : (0xFFFFFFFFu << ((p + 1) * 8));
        for (int i = tid; i < NPROP; i += 1024) {
            unsigned rk = rkey(sc[i]);
            if ((rk & pm) == pref) atomicAdd(&sh_hist[(rk >> (p * 8)) & 255], 1u);
        }
        __syncthreads();
        if (tid == 0) {
            int need = sh_need;
            unsigned acc = 0;
            for (int v = 0; v < 256; v++) {
                unsigned c = sh_hist[v];
                if (need <= (int)(acc + c)) {
                    sh_prefix = pref | ((unsigned)v << (p * 8));
                    sh_need = need - (int)acc;
                    break;
                }
                acc += c;
            }
        }
        __syncthreads();
    }
    unsigned cutoff = sh_prefix;
    if (tid == 0) sh_cnt = 0;
    __syncthreads();

    for (int i = tid; i < NPROP; i += 1024) {
        unsigned rk = rkey(sc[i]);
        if (rk <= cutoff) {
            int posn = atomicAdd(&sh_cnt, 1);
            if (posn < 4096)
                g_cand[b][posn] = ((unsigned long long)rk << 32) | (unsigned)i;
        }
    }
    __syncthreads();
    int total = sh_cnt; if (total > 4096) total = 4096;
    for (int i = tid; i < 4096; i += 1024)
        s[i] = (i < total) ? g_cand[b][i] : 0xFFFFFFFFFFFFFFFFull;
    __syncthreads();

    for (int k = 2; k <= 4096; k <<= 1) {
        for (int j = k >> 1; j > 0; j >>= 1) {
            for (int i = tid; i < 4096; i += 1024) {
                int l = i ^ j;
                if (l > i) {
                    unsigned long long a = s[i], c = s[l];
                    bool sw = ((i & k) == 0) ? (a > c) : (a < c);
                    if (sw) { s[i] = c; s[l] = a; }
                }
            }
            __syncthreads();
        }
    }

    for (int r2 = tid; r2 < PRE_NMS; r2 += 1024) {
        unsigned idx = (unsigned)(s[r2] & 0xFFFFFFFFull);
        const float* src = g_boxes + ((size_t)b * NPROP + idx) * 6;
        float* dst = g_sboxes + ((size_t)b * PRE_NMS + r2) * 6;
#pragma unroll
        for (int c = 0; c < 6; c++) dst[c] = src[c];
    }
}

// ---------------- NMS bitmask ----------------
__global__ void nms_mask_kernel() {
    int b = blockIdx.z, jb = blockIdx.x, ib = blockIdx.y, t = threadIdx.x;
    __shared__ float cb[64][6];
    const float* sb = g_sboxes + (size_t)b * PRE_NMS * 6;
    {
        const float* p = sb + (size_t)(jb * 64 + t) * 6;
#pragma unroll
        for (int c = 0; c < 6; c++) cb[t][c] = p[c];
    }
    __syncthreads();

    int i = ib * 64 + t;
    const float* p = sb + (size_t)i * 6;
    float x1 = p[0], y1 = p[1], z1 = p[2], x2 = p[3], y2 = p[4], z2 = p[5];
    float vi = (x2 - x1 + 1.f) * (y2 - y1 + 1.f) * (z2 - z1 + 1.f);
    unsigned long long bits = 0ull;
#pragma unroll 4
    for (int jj = 0; jj < 64; jj++) {
        float ix = fmaxf(fminf(x2, cb[jj][3]) - fmaxf(x1, cb[jj][0]) + 1.f, 0.f);
        float iy = fmaxf(fminf(y2, cb[jj][4]) - fmaxf(y1, cb[jj][1]) + 1.f, 0.f);
        float iz = fmaxf(fminf(z2, cb[jj][5]) - fmaxf(z1, cb[jj][2]) + 1.f, 0.f);
        float inter = ix * iy * iz;
        float vj = (cb[jj][3] - cb[jj][0] + 1.f) * (cb[jj][4] - cb[jj][1] + 1.f)
                 * (cb[jj][5] - cb[jj][2] + 1.f);
        float iou = inter / (vi + vj - inter);
        if (iou > NMS_TH) bits |= (1ull << jj);
    }
    g_mask[((size_t)b * PRE_NMS + i) * 32 + jb] = bits;
}

// ---------------- sequential keep-scan + output (16-deep prefetch ring) ----------------
__global__ void nms_scan_kernel(float* __restrict__ out) {
    int b = blockIdx.x;
    int lane = threadIdx.x;
    __shared__ unsigned short keep[POST_NMS];
    unsigned long long rem = 0ull;
    int nk = 0;
    const unsigned long long* mb = g_mask + (size_t)b * PRE_NMS * 32;

    unsigned long long pf[16];
#pragma unroll
    for (int u = 0; u < 16; u++) pf[u] = mb[(size_t)u * 32 + lane];

    for (int base = 0; base < PRE_NMS; base += 16) {
#pragma unroll
        for (int u = 0; u < 16; u++) {
            int i = base + u;
            unsigned long long w = __shfl_sync(0xffffffffu, rem, i >> 6);
            unsigned long long m = pf[u];
            int nx = i + 16;
            if (nx < PRE_NMS) pf[u] = mb[(size_t)nx * 32 + lane];
            if (!((w >> (i & 63)) & 1ull)) {
                if (lane == 0 && nk < POST_NMS) keep[nk] = (unsigned short)i;
                nk++;
                rem |= m;
            }
        }
    }
    __syncwarp();
    for (int r = lane; r < POST_NMS; r += 32) {
        float* o = out + ((size_t)b * POST_NMS + r) * 7;
        o[0] = (float)b;
        if (r < nk) {
            int i = keep[r];
            const float* bx = g_sboxes + ((size_t)b * PRE_NMS + i) * 6;
#pragma unroll
            for (int c = 0; c < 6; c++) o[1 + c] = bx[c];
        } else {
#pragma unroll
            for (int c = 0; c < 6; c++) o[1 + c] = 0.f;
        }
    }
}

// ---------------- launch ----------------
extern "C" void kernel_launch(void* const* d_in, const int* in_sizes, int n_in,
                              void* d_out, int out_size) {
    const float* base_feat = (const float*)d_in[0];
    const float* im_info   = (const float*)d_in[1];
    const float* W_conv    = (const float*)d_in[4];
    const float* b_conv    = (const float*)d_in[5];
    const float* W_cls     = (const float*)d_in[6];
    const float* b_cls     = (const float*)d_in[7];
    const float* W_bbox    = (const float*)d_in[8];
    const float* b_bbox    = (const float*)d_in[9];
    float* out = (float*)d_out;

    float *p_wh, *p_bh, *p_colc, *p_xc, *p_hc;
    int* p_nc;
    cudaGetSymbolAddress((void**)&p_wh,   g_wh);
    cudaGetSymbolAddress((void**)&p_bh,   g_bh);
    cudaGetSymbolAddress((void**)&p_colc, g_colc);
    cudaGetSymbolAddress((void**)&p_xc,   g_xc);
    cudaGetSymbolAddress((void**)&p_hc,   g_hc);
    cudaGetSymbolAddress((void**)&p_nc,   g_nc);

    cudaFuncSetAttribute(conv_emu_kernel, cudaFuncAttributeMaxDynamicSharedMemorySize, SMEM_EMU);

    zero_fp_kernel<<<(int)((FPAD / 8 + 255) / 256), 256>>>();
    tsplit_kernel<<<BATCH * DD * HH, 256>>>(base_feat);
    a_reord_kernel<<<(COUT * KDIM + 255) / 256, 256>>>(W_conv);
    {   // emu conv (implicit im2col, single-bf16 term, 5-stage pipeline)
        dim3 grid(COUT / 128, NCOL / 128);
        conv_emu_kernel<<<grid, 256, SMEM_EMU>>>(b_conv);
    }
    pack_head<<<(HROWS * 512 + 255) / 256, 256>>>(W_cls, b_cls, W_bbox, b_bbox);
    head18_kernel<<<NCOL / 128, 128>>>();
    escore_kernel<<<(BATCH * NPROP + 255) / 256, 256>>>();
    cutoff_kernel<<<BATCH, 1024>>>();
    flag_kernel<<<(BATCH * NPROP + 255) / 256, 256>>>();
    compact_kernel<<<1, 1024>>>();
    {
        dim3 grid(CCAP / 32, 27);
        gather_kernel<<<grid, 256>>>(base_feat);
    }
    {   // exact conv on compacted columns (32x64 tiles, R1-identical numerics)
        dim3 grid(CW / 64, COUT / 32);
        exact32x64<<<grid, 128>>>(W_conv, p_colc, p_xc, b_conv, COUT, CW, KDIM, 1, p_nc + 2);
    }
    {   // exact heads on compacted columns
        dim3 grid(CW / 64, (HROWS + 31) / 32);
        exact32x64<<<grid, 128>>>(p_wh, p_xc, p_hc, p_bh, HROWS, CW, 512, 0, p_nc + 2);
    }
    decode_cand_kernel<<<(CCAP * NANCH + 255) / 256, 256>>>(im_info);
    select_topk_kernel<<<BATCH, 1024>>>();
    {
        dim3 grid(PRE_NMS / 64, PRE_NMS / 64, BATCH);
        nms_mask_kernel<<<grid, 64>>>();
    }
    nms_scan_kernel<<<BATCH, 32>>>(out);
}

// round 17
// speedup vs baseline: 1.1876x; 1.0041x over previous
#include <cuda_runtime.h>
#include <cuda_bf16.h>
#include <math.h>
#include <stdint.h>

// ---------------- problem constants ----------------
#define BATCH   2
#define CIN     128
#define COUT    512
#define DD      8
#define HH      32
#define WW      32
#define POS     (DD*HH*WW)          // 8192
#define NCOL    (BATCH*POS)         // 16384
#define KDIM    (CIN*27)            // 3456
#define NANCH   9
#define NPROP   (POS*NANCH)         // 73728 per batch
#define PRE_NMS 2048
#define POST_NMS 300
#define NMS_TH  0.7f
#define HROWS   72
#define CLSROWS 18
#define MARGIN  4e-3f
#define CCAP    8192
#define CW      8192

// emu conv tiling (A bf16 x B bf16, single term), K reordered as (off, c)
#define TILE_K    32
#define KITERS    (KDIM/TILE_K)     // 108
#define PLANE_W   (128*20)
#define STAGE_W   (2*PLANE_W)       // A, B1
#define STAGE_B   (STAGE_W*4)       // 20480 bytes
#define NSTG      5                 // slots; prefetch distance 4
#define SMEM_EMU  (NSTG*STAGE_B)    // 102400

// padded transposed feature map: [B][D+2][H+2][W+2][C]
#define FPD     (DD+2)
#define FPH     (HH+2)
#define FPW     (WW+2)
#define FPAD    ((size_t)BATCH*FPD*FPH*FPW*CIN)

// ---------------- static scratch ----------------
__device__ __align__(128) __nv_bfloat16 g_fp1[FPAD];
__device__ __align__(128) __nv_bfloat16 g_ar [(size_t)COUT * KDIM];
__device__ float g_xe  [(size_t)COUT * NCOL];
__device__ float g_h   [(size_t)CLSROWS * NCOL];
__device__ float g_colc[(size_t)KDIM * CW];
__device__ float g_xc  [(size_t)COUT * CW];
__device__ float g_hc  [(size_t)HROWS * CW];
__device__ float g_wh  [HROWS * 512];
__device__ float g_bh  [HROWS];
__device__ float g_escore[BATCH * NPROP];
__device__ float g_thr[BATCH];
__device__ int   g_pflag[BATCH * POS];
__device__ int   g_plist[CCAP];
__device__ int   g_nc[4];
__device__ float g_scores[BATCH * NPROP];
__device__ float g_boxes [(size_t)BATCH * NPROP * 6];
__device__ unsigned long long g_cand[BATCH][4096];
__device__ float g_sboxes[(size_t)BATCH * PRE_NMS * 6];
__device__ unsigned long long g_mask[(size_t)BATCH * PRE_NMS * 32];

// ---------------- helpers ----------------
__device__ __forceinline__ uint32_t smem_u32(const void* p) {
    uint32_t a;
    asm("{ .reg .u64 t; cvta.to.shared.u64 t, %1; cvt.u32.u64 %0, t; }" : "=r"(a) : "l"(p));
    return a;
}
__device__ __forceinline__ void cp_async16(uint32_t dst, const void* src) {
    asm volatile("cp.async.cg.shared.global [%0], [%1], 16;" :: "r"(dst), "l"(src));
}
__device__ __forceinline__ void cp_commit() { asm volatile("cp.async.commit_group;" ::: "memory"); }
__device__ __forceinline__ void cp_wait3()  { asm volatile("cp.async.wait_group 3;" ::: "memory"); }
__device__ __forceinline__ void cp_wait2()  { asm volatile("cp.async.wait_group 2;" ::: "memory"); }
__device__ __forceinline__ void cp_wait1()  { asm volatile("cp.async.wait_group 1;" ::: "memory"); }
__device__ __forceinline__ void cp_wait0()  { asm volatile("cp.async.wait_group 0;" ::: "memory"); }

__device__ __forceinline__ void mma_bf16(float c[4], const uint32_t a[4], const uint32_t b[2]) {
    asm volatile("mma.sync.aligned.m16n8k16.row.col.f32.bf16.bf16.f32 "
        "{%0,%1,%2,%3}, {%4,%5,%6,%7}, {%8,%9}, {%0,%1,%2,%3};"
        : "+f"(c[0]), "+f"(c[1]), "+f"(c[2]), "+f"(c[3])
        : "r"(a[0]), "r"(a[1]), "r"(a[2]), "r"(a[3]), "r"(b[0]), "r"(b[1]));
}
__device__ __forceinline__ unsigned int rkey(float f) {
    unsigned u = __float_as_uint(f);
    u = (u & 0x80000000u) ? ~u : (u | 0x80000000u);
    return ~u;
}

// ---------------- im2col value (exact path; original K order c*27+off) ----------------
__device__ __forceinline__ float im2col_val(const float* __restrict__ bf, int b, int pos, int k) {
    int c = k / 27; int rem = k - c * 27;
    int kd = rem / 9, kh = (rem % 9) / 3, kw = rem % 3;
    int d = pos >> 10, h = (pos >> 5) & 31, w = pos & 31;
    int zd = d + kd - 1, zh = h + kh - 1, zw = w + kw - 1;
    if ((unsigned)zd < DD && (unsigned)zh < HH && (unsigned)zw < WW)
        return bf[(((size_t)(b * CIN + c) * DD + zd) * HH + zh) * WW + zw];
    return 0.f;
}

// ---------------- fused prep: zero halo + weight reorder + head pack ----------------
__global__ void prep_kernel(const float* __restrict__ Wc,
                            const float* __restrict__ Wcls, const float* __restrict__ bcls,
                            const float* __restrict__ Wb,   const float* __restrict__ bb) {
    int idx = blockIdx.x * 256 + threadIdx.x;
    if (idx < COUT * KDIM) {
        int m = idx / KDIM, k = idx - m * KDIM;
        int off = k >> 7, c = k & 127;
        g_ar[idx] = __float2bfloat16_rn(Wc[(size_t)m * KDIM + c * 27 + off]);
    }
    if ((size_t)idx * 8 < FPAD)
        *(uint4*)(g_fp1 + (size_t)idx * 8) = make_uint4(0, 0, 0, 0);
    if (idx < HROWS * 512) {
        int row = idx / 512, col = idx % 512;
        g_wh[idx] = (row < 18) ? Wcls[row * 512 + col] : Wb[(row - 18) * 512 + col];
    }
    if (idx < HROWS) g_bh[idx] = (idx < 18) ? bcls[idx] : bb[idx - 18];
}

// ---------------- transpose + bf16 round ----------------
__global__ void tsplit_kernel(const float* __restrict__ bf) {
    __shared__ float tile[128][33];
    int blk = blockIdx.x;
    int b = blk >> 8;
    int d = (blk >> 5) & 7;
    int h = blk & 31;
    int t = threadIdx.x;

    int w = t & 31, cr = t >> 5;
#pragma unroll
    for (int i = 0; i < 16; i++) {
        int c = i * 8 + cr;
        tile[c][w] = bf[(((size_t)(b * CIN + c) * DD + d) << 10) + h * 32 + w];
    }
    __syncthreads();

    int c2 = t & 127, wr = t >> 7;
    size_t obase = ((((size_t)b * FPD + d + 1) * FPH + h + 1) * FPW + 1) * 128;
#pragma unroll
    for (int i = 0; i < 16; i++) {
        int w2 = i * 2 + wr;
        g_fp1[obase + (size_t)w2 * 128 + c2] = __float2bfloat16_rn(tile[c2][w2]);
    }
}

// ---------------- emu conv: implicit im2col, A bf16 x B bf16, single-sync pipeline ----------------
__device__ __forceinline__ void load_stage_emu(uint32_t sbase, int it, int m0,
                                               int bb, int dd, int h0, int tid) {
    int k0 = it * TILE_K;
    int off = k0 >> 7;
    int c0  = k0 & 127;
    int kd = off / 9; int r9 = off - kd * 9;
    int kh = r9 / 3;  int kw = r9 - kh * 3;

#pragma unroll
    for (int i = 0; i < 2; i++) {
        int cwp = i * 256 + tid;
        int row = cwp >> 2, quad = cwp & 3;
        uint32_t doff = (uint32_t)(row * 80 + quad * 16);
        cp_async16(sbase + doff, g_ar + (size_t)(m0 + row) * KDIM + k0 + quad * 8);
    }
#pragma unroll
    for (int i = 0; i < 2; i++) {
        int cwp = i * 256 + tid;
        int row = cwp >> 2, quad = cwp & 3;
        int h = h0 + (row >> 5);
        int w = row & 31;
        size_t base = ((((size_t)bb * FPD + dd + kd) * FPH + h + kh) * FPW + (w + kw)) * 128
                    + c0 + quad * 8;
        uint32_t doff = (uint32_t)(PLANE_W * 4 + row * 80 + quad * 16);
        cp_async16(sbase + doff, g_fp1 + base);
    }
    cp_commit();
}

__global__ __launch_bounds__(256)
void conv_emu_kernel(const float* __restrict__ bias) {
    extern __shared__ __align__(16) uint32_t smem[];
    const int tid  = threadIdx.x;
    const int wid  = tid >> 5;
    const int lane = tid & 31;
    const int m0 = blockIdx.x * 128;
    const int n0 = blockIdx.y * 128;
    const int m_off = (wid >> 1) * 32;
    const int n_off = (wid & 1) * 64;
    const int qr = lane >> 2, qc = lane & 3;
    uint32_t sb = smem_u32(smem);

    const int bb = n0 >> 13;
    const int pos0 = n0 & (POS - 1);
    const int dd = pos0 >> 10;
    const int h0 = (pos0 >> 5) & 31;

    float acc[2][8][4];
#pragma unroll
    for (int i = 0; i < 2; i++)
#pragma unroll
        for (int j = 0; j < 8; j++)
#pragma unroll
            for (int t = 0; t < 4; t++) acc[i][j][t] = 0.f;

    // prologue: prefetch distance 4 (into slots 0..3 of 5)
#pragma unroll
    for (int s = 0; s < 4; s++)
        load_stage_emu(sb + s * STAGE_B, s, m0, bb, dd, h0, tid);

    for (int it = 0; it < KITERS; it++) {
        if (it < KITERS - 3) cp_wait3();
        else if (it < KITERS - 2) cp_wait2();
        else if (it < KITERS - 1) cp_wait1();
        else cp_wait0();
        __syncthreads();          // single barrier per iteration

        // prefetch into slot (it+4)%5 — distinct from the slot being computed
        if (it + 4 < KITERS)
            load_stage_emu(sb + ((it + 4) % NSTG) * STAGE_B, it + 4, m0, bb, dd, h0, tid);

        const uint32_t* S = smem + (it % NSTG) * STAGE_W;
        const uint32_t* A1 = S;
        const uint32_t* B1 = S + PLANE_W;

#pragma unroll
        for (int q = 0; q < 2; q++) {
            int w0 = q * 8 + qc;
            uint32_t a1[2][4];
#pragma unroll
            for (int i = 0; i < 2; i++) {
                int r = m_off + i * 16 + qr;
                a1[i][0] = A1[r * 20 + w0];       a1[i][1] = A1[(r + 8) * 20 + w0];
                a1[i][2] = A1[r * 20 + w0 + 4];   a1[i][3] = A1[(r + 8) * 20 + w0 + 4];
            }
#pragma unroll
            for (int j = 0; j < 8; j++) {
                int n = n_off + j * 8 + qr;
                uint32_t b1[2] = { B1[n * 20 + w0], B1[n * 20 + w0 + 4] };
#pragma unroll
                for (int i = 0; i < 2; i++)
                    mma_bf16(acc[i][j], a1[i], b1);
            }
        }
    }

#pragma unroll
    for (int i = 0; i < 2; i++) {
        int r0 = m0 + m_off + i * 16 + qr;
        float b0 = bias[r0], b1v = bias[r0 + 8];
#pragma unroll
        for (int j = 0; j < 8; j++) {
            int c0 = n0 + n_off + j * 8 + qc * 2;
            float2 v0, v1;
            v0.x = fmaxf(acc[i][j][0] + b0, 0.f);
            v0.y = fmaxf(acc[i][j][1] + b0, 0.f);
            v1.x = fmaxf(acc[i][j][2] + b1v, 0.f);
            v1.y = fmaxf(acc[i][j][3] + b1v, 0.f);
            *(float2*)(g_xe + (size_t)r0 * NCOL + c0) = v0;
            *(float2*)(g_xe + (size_t)(r0 + 8) * NCOL + c0) = v1;
        }
    }
}

// ---------------- emu heads: 18 cls rows, dedicated kernel ----------------
__global__ __launch_bounds__(128)
void head18_kernel() {
    __shared__ float w[CLSROWS * 512];
    int t = threadIdx.x;
    for (int i = t; i < CLSROWS * 512; i += 128) w[i] = g_wh[i];
    __syncthreads();
    int n = blockIdx.x * 128 + t;
    float acc[CLSROWS];
#pragma unroll
    for (int r = 0; r < CLSROWS; r++) acc[r] = g_bh[r];
    for (int k = 0; k < 512; k++) {
        float xv = g_xe[(size_t)k * NCOL + n];
#pragma unroll
        for (int r = 0; r < CLSROWS; r++) acc[r] = fmaf(w[r * 512 + k], xv, acc[r]);
    }
#pragma unroll
    for (int r = 0; r < CLSROWS; r++) g_h[(size_t)r * NCOL + n] = acc[r];
}

// ---------------- exact GEMM, 32m x 64n tiles (bit-identical k-ascending fmaf chains) ----------------
__global__ __launch_bounds__(128)
void exact32x64(const float* __restrict__ A, const float* __restrict__ B,
                float* __restrict__ C, const float* __restrict__ bias,
                int M, int N, int K, int doRelu, const int* __restrict__ nlim) {
    if (blockIdx.x * 64 >= *nlim) return;
    __shared__ float As[2][8][32];
    __shared__ float Bs[2][8][64];
    const int tid = threadIdx.x;
    const int m0 = blockIdx.y * 32;
    const int n0 = blockIdx.x * 64;
    const int mg = tid >> 4, ng = tid & 15;
    const int am = tid & 31, akq = (tid >> 5) * 4;
    const int bk = tid >> 4, bn4 = (tid & 15) * 4;

    float acc[4][4];
#pragma unroll
    for (int i = 0; i < 4; i++)
#pragma unroll
        for (int j = 0; j < 4; j++) acc[i][j] = 0.f;

    float4 av = make_float4(0.f, 0.f, 0.f, 0.f), bv;
    {
        if (tid < 64) {
            int gm = m0 + am;
            if (gm < M) av = *(const float4*)(A + (size_t)gm * K + akq);
        }
        bv = *(const float4*)(B + (size_t)bk * N + n0 + bn4);
        if (tid < 64) {
            As[0][akq + 0][am] = av.x; As[0][akq + 1][am] = av.y;
            As[0][akq + 2][am] = av.z; As[0][akq + 3][am] = av.w;
        }
        *(float4*)&Bs[0][bk][bn4] = bv;
    }
    __syncthreads();

    int cur = 0;
    for (int kt = 8; kt < K; kt += 8) {
        av = make_float4(0.f, 0.f, 0.f, 0.f);
        if (tid < 64) {
            int gm = m0 + am;
            if (gm < M) av = *(const float4*)(A + (size_t)gm * K + kt + akq);
        }
        bv = *(const float4*)(B + (size_t)(kt + bk) * N + n0 + bn4);

#pragma unroll
        for (int kk = 0; kk < 8; kk++) {
            float4 a = *(const float4*)&As[cur][kk][mg * 4];
            float4 b = *(const float4*)&Bs[cur][kk][ng * 4];
            acc[0][0] = fmaf(a.x, b.x, acc[0][0]); acc[0][1] = fmaf(a.x, b.y, acc[0][1]);
            acc[0][2] = fmaf(a.x, b.z, acc[0][2]); acc[0][3] = fmaf(a.x, b.w, acc[0][3]);
            acc[1][0] = fmaf(a.y, b.x, acc[1][0]); acc[1][1] = fmaf(a.y, b.y, acc[1][1]);
            acc[1][2] = fmaf(a.y, b.z, acc[1][2]); acc[1][3] = fmaf(a.y, b.w, acc[1][3]);
            acc[2][0] = fmaf(a.z, b.x, acc[2][0]); acc[2][1] = fmaf(a.z, b.y, acc[2][1]);
            acc[2][2] = fmaf(a.z, b.z, acc[2][2]); acc[2][3] = fmaf(a.z, b.w, acc[2][3]);
            acc[3][0] = fmaf(a.w, b.x, acc[3][0]); acc[3][1] = fmaf(a.w, b.y, acc[3][1]);
            acc[3][2] = fmaf(a.w, b.z, acc[3][2]); acc[3][3] = fmaf(a.w, b.w, acc[3][3]);
        }
        int nxt = cur ^ 1;
        if (tid < 64) {
            As[nxt][akq + 0][am] = av.x; As[nxt][akq + 1][am] = av.y;
            As[nxt][akq + 2][am] = av.z; As[nxt][akq + 3][am] = av.w;
        }
        *(float4*)&Bs[nxt][bk][bn4] = bv;
        __syncthreads();
        cur = nxt;
    }
#pragma unroll
    for (int kk = 0; kk < 8; kk++) {
        float4 a = *(const float4*)&As[cur][kk][mg * 4];
        float4 b = *(const float4*)&Bs[cur][kk][ng * 4];
        acc[0][0] = fmaf(a.x, b.x, acc[0][0]); acc[0][1] = fmaf(a.x, b.y, acc[0][1]);
        acc[0][2] = fmaf(a.x, b.z, acc[0][2]); acc[0][3] = fmaf(a.x, b.w, acc[0][3]);
        acc[1][0] = fmaf(a.y, b.x, acc[1][0]); acc[1][1] = fmaf(a.y, b.y, acc[1][1]);
        acc[1][2] = fmaf(a.y, b.z, acc[1][2]); acc[1][3] = fmaf(a.y, b.w, acc[1][3]);
        acc[2][0] = fmaf(a.z, b.x, acc[2][0]); acc[2][1] = fmaf(a.z, b.y, acc[2][1]);
        acc[2][2] = fmaf(a.z, b.z, acc[2][2]); acc[2][3] = fmaf(a.z, b.w, acc[2][3]);
        acc[3][0] = fmaf(a.w, b.x, acc[3][0]); acc[3][1] = fmaf(a.w, b.y, acc[3][1]);
        acc[3][2] = fmaf(a.w, b.z, acc[3][2]); acc[3][3] = fmaf(a.w, b.w, acc[3][3]);
    }

#pragma unroll
    for (int i = 0; i < 4; i++) {
        int gm = m0 + mg * 4 + i;
        if (gm >= M) continue;
        float bb = bias[gm];
        float4 v;
        v.x = acc[i][0] + bb; v.y = acc[i][1] + bb;
        v.z = acc[i][2] + bb; v.w = acc[i][3] + bb;
        if (doRelu) {
            v.x = fmaxf(v.x, 0.f); v.y = fmaxf(v.y, 0.f);
            v.z = fmaxf(v.z, 0.f); v.w = fmaxf(v.w, 0.f);
        }
        *(float4*)(C + (size_t)gm * N + n0 + ng * 4) = v;
    }
}

// ---------------- emu scores + clear ----------------
__global__ void escore_kernel() {
    int idx = blockIdx.x * 256 + threadIdx.x;
    if (idx < BATCH * POS) g_pflag[idx] = 0;
    if (idx >= BATCH * NPROP) return;
    g_scores[idx] = 0.f;
    int b = idx / NPROP;
    int i = idx - b * NPROP;
    int pos = i / NANCH;
    int a = i - pos * NANCH;
    int n = b * POS + pos;
    float l0 = g_h[(size_t)a * NCOL + n];
    float l1 = g_h[(size_t)(NANCH + a) * NCOL + n];
    float mx = fmaxf(l0, l1);
    float e0 = expf(l0 - mx), e1 = expf(l1 - mx);
    g_escore[idx] = e1 / (e0 + e1);
}

// ---------------- emu cutoff (2048th) ----------------
__global__ __launch_bounds__(1024)
void cutoff_kernel() {
    const int b = blockIdx.x;
    const int tid = threadIdx.x;
    const float* sc = g_escore + (size_t)b * NPROP;
    __shared__ unsigned sh_hist[256];
    __shared__ unsigned sh_prefix;
    __shared__ int sh_need;
    if (tid == 0) { sh_prefix = 0; sh_need = PRE_NMS; }
    __syncthreads();
    for (int p = 3; p >= 0; p--) {
        for (int v = tid; v < 256; v += 1024) sh_hist[v] = 0;
        __syncthreads();
        unsigned pref = sh_prefix;
        unsigned pm = (p == 3) ? 0u : (0xFFFFFFFFu << ((p + 1) * 8));
        for (int i = tid; i < NPROP; i += 1024) {
            unsigned rk = rkey(sc[i]);
            if ((rk & pm) == pref) atomicAdd(&sh_hist[(rk >> (p * 8)) & 255], 1u);
        }
        __syncthreads();
        if (tid == 0) {
            int need = sh_need;
            unsigned acc = 0;
            for (int v = 0; v < 256; v++) {
                unsigned c = sh_hist[v];
                if (need <= (int)(acc + c)) {
                    sh_prefix = pref | ((unsigned)v << (p * 8));
                    sh_need = need - (int)acc;
                    break;
                }
                acc += c;
            }
        }
        __syncthreads();
    }
    if (tid == 0) {
        unsigned m = ~sh_prefix;
        float cf = __uint_as_float(m & 0x7FFFFFFFu);
        g_thr[b] = cf - MARGIN;
    }
}

// ---------------- candidate flags ----------------
__global__ void flag_kernel() {
    int idx = blockIdx.x * 256 + threadIdx.x;
    if (idx >= BATCH * NPROP) return;
    int b = idx / NPROP;
    if (g_escore[idx] >= g_thr[b]) {
        int pos = (idx - b * NPROP) / NANCH;
        g_pflag[b * POS + pos] = 1;
    }
}

// ---------------- compaction ----------------
__global__ __launch_bounds__(1024)
void compact_kernel() {
    __shared__ int warp_sums[32];
    __shared__ int base_off;
    int tid = threadIdx.x;
    int lane = tid & 31, wrp = tid >> 5;
    if (tid == 0) base_off = 0;
    __syncthreads();
    for (int b = 0; b < BATCH; b++) {
        int cnt = 0;
        int mypos[8];
#pragma unroll
        for (int u = 0; u < 8; u++) {
            int pos = tid * 8 + u;
            if (g_pflag[b * POS + pos]) mypos[cnt++] = pos;
        }
        int v = cnt;
#pragma unroll
        for (int o = 1; o < 32; o <<= 1) {
            int t = __shfl_up_sync(0xffffffffu, v, o);
            if (lane >= o) v += t;
        }
        if (lane == 31) warp_sums[wrp] = v;
        __syncthreads();
        if (wrp == 0) {
            int wv = warp_sums[lane];
#pragma unroll
            for (int o = 1; o < 32; o <<= 1) {
                int t = __shfl_up_sync(0xffffffffu, wv, o);
                if (lane >= o) wv += t;
            }
            warp_sums[lane] = wv;
        }
        __syncthreads();
        int excl = v - cnt + (wrp ? warp_sums[wrp - 1] : 0);
        int bo = base_off;
        for (int u = 0; u < cnt; u++) {
            int slot = bo + excl + u;
            if (slot < CCAP) g_plist[slot] = b * POS + mypos[u];
        }
        __syncthreads();
        if (tid == 0) {
            int tot = warp_sums[31];
            int nb = base_off + tot; if (nb > CCAP) nb = CCAP;
            if (b == 0) g_nc[0] = nb;
            base_off = nb;
            if (b == BATCH - 1) {
                g_nc[1] = base_off;
                g_nc[2] = (base_off + 63) & ~63;
            }
        }
        __syncthreads();
    }
}

// ---------------- gather (coalesced writes) ----------------
__global__ void gather_kernel(const float* __restrict__ bf) {
    int j0 = blockIdx.x * 32;
    if (j0 >= g_nc[1]) return;
    int jl = threadIdx.x & 31;
    int kl = threadIdx.x >> 5;
    int j = j0 + jl;
    int n = g_plist[j];
    int b = n >> 13, pos = n & (POS - 1);
#pragma unroll
    for (int kk = 0; kk < 16; kk++) {
        int k = blockIdx.y * 128 + kl * 16 + kk;
        g_colc[(size_t)k * CW + j] = im2col_val(bf, b, pos, k);
    }
}

// ---------------- exact decode for candidates ----------------
__global__ void decode_cand_kernel(const float* __restrict__ im_info) {
    int idx = blockIdx.x * 256 + threadIdx.x;
    int cidx = idx / NANCH;
    if (cidx >= g_nc[1]) return;
    int a = idx - cidx * NANCH;
    int n = g_plist[cidx];
    int b = n >> 13, pos = n & (POS - 1);
    int i = pos * NANCH + a;

    float l0 = g_hc[(size_t)a * CW + cidx];
    float l1 = g_hc[(size_t)(NANCH + a) * CW + cidx];
    float mx = fmaxf(l0, l1);
    float e0 = expf(l0 - mx), e1 = expf(l1 - mx);
    g_scores[(size_t)b * NPROP + i] = e1 / (e0 + e1);

    const float* hd = g_hc + (size_t)(18 + a * 6) * CW + cidx;
    float dx = hd[0 * (size_t)CW], dy = hd[1 * (size_t)CW], dz = hd[2 * (size_t)CW];
    float dw = hd[3 * (size_t)CW], dh = hd[4 * (size_t)CW], dd = hd[5 * (size_t)CW];

    int wp = pos & 31, hp = (pos >> 5) & 31, dp = pos >> 10;
    float s = 4.f * (float)(1 << (a % 3));
    float r = 0.5f * (float)(1 << (a / 3));
    float wsz = 8.f * s;
    float dsz = 8.f * s * r;
    const float ctr = 3.5f;
    float sx = wp * 8.f, sy = hp * 8.f, sz = dp * 8.f;

    float x1 = sx + ctr - 0.5f * (wsz - 1.f), x2 = sx + ctr + 0.5f * (wsz - 1.f);
    float y1 = sy + ctr - 0.5f * (wsz - 1.f), y2 = sy + ctr + 0.5f * (wsz - 1.f);
    float z1 = sz + ctr - 0.5f * (dsz - 1.f), z2 = sz + ctr + 0.5f * (dsz - 1.f);

    float aw = x2 - x1 + 1.f, ah = y2 - y1 + 1.f, ad = z2 - z1 + 1.f;
    float cx = x1 + 0.5f * aw, cy = y1 + 0.5f * ah, cz = z1 + 0.5f * ad;

    float pcx = dx * aw + cx, pcy = dy * ah + cy, pcz = dz * ad + cz;
    float pw = expf(dw) * aw, ph = expf(dh) * ah, pd = expf(dd) * ad;

    float ox1 = pcx - 0.5f * pw, oy1 = pcy - 0.5f * ph, oz1 = pcz - 0.5f * pd;
    float ox2 = pcx + 0.5f * pw, oy2 = pcy + 0.5f * ph, oz2 = pcz + 0.5f * pd;

    float hix = im_info[b * 3 + 2] - 1.f;
    float hiy = im_info[b * 3 + 1] - 1.f;
    float hiz = im_info[b * 3 + 0] - 1.f;
    ox1 = fminf(fmaxf(ox1, 0.f), hix); ox2 = fminf(fmaxf(ox2, 0.f), hix);
    oy1 = fminf(fmaxf(oy1, 0.f), hiy); oy2 = fminf(fmaxf(oy2, 0.f), hiy);
    oz1 = fminf(fmaxf(oz1, 0.f), hiz); oz2 = fminf(fmaxf(oz2, 0.f), hiz);

    float* ob = g_boxes + ((size_t)b * NPROP + i) * 6;
    ob[0] = ox1; ob[1] = oy1; ob[2] = oz1; ob[3] = ox2; ob[4] = oy2; ob[5] = oz2;
}

// ---------------- top-2048 select (exact jax top_k order) ----------------
__global__ __launch_bounds__(1024)
void select_topk_kernel() {
    const int b = blockIdx.x;
    const int tid = threadIdx.x;
    const float* sc = g_scores + (size_t)b * NPROP;

    __shared__ unsigned sh_hist[256];
    __shared__ unsigned sh_prefix;
    __shared__ int sh_need;
    __shared__ int sh_cnt;
    __shared__ unsigned long long s[4096];

    if (tid == 0) { sh_prefix = 0; sh_need = PRE_NMS; }
    __syncthreads();

    for (int p = 3; p >= 0; p--) {
        for (int v = tid; v < 256; v += 1024) sh_hist[v] = 0;
        __syncthreads();
        unsigned pref = sh_prefix;
        unsigned pm = (p == 3) ? 0u : (0xFFFFFFFFu << ((p + 1) * 8));
        for (int i = tid; i < NPROP; i += 1024) {
            unsigned rk = rkey(sc[i]);
            if ((rk & pm) == pref) atomicAdd(&sh_hist[(rk >> (p * 8)) & 255], 1u);
        }
        __syncthreads();
        if (tid == 0) {
            int need = sh_need;
            unsigned acc = 0;
            for (int v = 0; v < 256; v++) {
                unsigned c = sh_hist[v];
                if (need <= (int)(acc + c)) {
                    sh_prefix = pref | ((unsigned)v << (p * 8));
                    sh_need = need - (int)acc;
                    break;
                }
                acc += c;
            }
        }
        __syncthreads();
    }
    unsigned cutoff = sh_prefix;
    if (tid == 0) sh_cnt = 0;
    __syncthreads();

    for (int i = tid; i < NPROP; i += 1024) {
        unsigned rk = rkey(sc[i]);
        if (rk <= cutoff) {
            int posn = atomicAdd(&sh_cnt, 1);
            if (posn < 4096)
                g_cand[b][posn] = ((unsigned long long)rk << 32) | (unsigned)i;
        }
    }
    __syncthreads();
    int total = sh_cnt; if (total > 4096) total = 4096;
    for (int i = tid; i < 4096; i += 1024)
        s[i] = (i < total) ? g_cand[b][i] : 0xFFFFFFFFFFFFFFFFull;
    __syncthreads();

    for (int k = 2; k <= 4096; k <<= 1) {
        for (int j = k >> 1; j > 0; j >>= 1) {
            for (int i = tid; i < 4096; i += 1024) {
                int l = i ^ j;
                if (l > i) {
                    unsigned long long a = s[i], c = s[l];
                    bool sw = ((i & k) == 0) ? (a > c) : (a < c);
                    if (sw) { s[i] = c; s[l] = a; }
                }
            }
            __syncthreads();
        }
    }

    for (int r2 = tid; r2 < PRE_NMS; r2 += 1024) {
        unsigned idx = (unsigned)(s[r2] & 0xFFFFFFFFull);
        const float* src = g_boxes + ((size_t)b * NPROP + idx) * 6;
        float* dst = g_sboxes + ((size_t)b * PRE_NMS + r2) * 6;
#pragma unroll
        for (int c = 0; c < 6; c++) dst[c] = src[c];
    }
}

// ---------------- NMS bitmask ----------------
__global__ void nms_mask_kernel() {
    int b = blockIdx.z, jb = blockIdx.x, ib = blockIdx.y, t = threadIdx.x;
    __shared__ float cb[64][6];
    const float* sb = g_sboxes + (size_t)b * PRE_NMS * 6;
    {
        const float* p = sb + (size_t)(jb * 64 + t) * 6;
#pragma unroll
        for (int c = 0; c < 6; c++) cb[t][c] = p[c];
    }
    __syncthreads();

    int i = ib * 64 + t;
    const float* p = sb + (size_t)i * 6;
    float x1 = p[0], y1 = p[1], z1 = p[2], x2 = p[3], y2 = p[4], z2 = p[5];
    float vi = (x2 - x1 + 1.f) * (y2 - y1 + 1.f) * (z2 - z1 + 1.f);
    unsigned long long bits = 0ull;
#pragma unroll 4
    for (int jj = 0; jj < 64; jj++) {
        float ix = fmaxf(fminf(x2, cb[jj][3]) - fmaxf(x1, cb[jj][0]) + 1.f, 0.f);
        float iy = fmaxf(fminf(y2, cb[jj][4]) - fmaxf(y1, cb[jj][1]) + 1.f, 0.f);
        float iz = fmaxf(fminf(z2, cb[jj][5]) - fmaxf(z1, cb[jj][2]) + 1.f, 0.f);
        float inter = ix * iy * iz;
        float vj = (cb[jj][3] - cb[jj][0] + 1.f) * (cb[jj][4] - cb[jj][1] + 1.f)
                 * (cb[jj][5] - cb[jj][2] + 1.f);
        float iou = inter / (vi + vj - inter);
        if (iou > NMS_TH) bits |= (1ull << jj);
    }
    g_mask[((size_t)b * PRE_NMS + i) * 32 + jb] = bits;
}

// ---------------- sequential keep-scan + output (16-deep prefetch ring) ----------------
__global__ void nms_scan_kernel(float* __restrict__ out) {
    int b = blockIdx.x;
    int lane = threadIdx.x;
    __shared__ unsigned short keep[POST_NMS];
    unsigned long long rem = 0ull;
    int nk = 0;
    const unsigned long long* mb = g_mask + (size_t)b * PRE_NMS * 32;

    unsigned long long pf[16];
#pragma unroll
    for (int u = 0; u < 16; u++) pf[u] = mb[(size_t)u * 32 + lane];

    for (int base = 0; base < PRE_NMS; base += 16) {
#pragma unroll
        for (int u = 0; u < 16; u++) {
            int i = base + u;
            unsigned long long w = __shfl_sync(0xffffffffu, rem, i >> 6);
            unsigned long long m = pf[u];
            int nx = i + 16;
            if (nx < PRE_NMS) pf[u] = mb[(size_t)nx * 32 + lane];
            if (!((w >> (i & 63)) & 1ull)) {
                if (lane == 0 && nk < POST_NMS) keep[nk] = (unsigned short)i;
                nk++;
                rem |= m;
            }
        }
    }
    __syncwarp();
    for (int r = lane; r < POST_NMS; r += 32) {
        float* o = out + ((size_t)b * POST_NMS + r) * 7;
        o[0] = (float)b;
        if (r < nk) {
            int i = keep[r];
            const float* bx = g_sboxes + ((size_t)b * PRE_NMS + i) * 6;
#pragma unroll
            for (int c = 0; c < 6; c++) o[1 + c] = bx[c];
        } else {
#pragma unroll
            for (int c = 0; c < 6; c++) o[1 + c] = 0.f;
        }
    }
}

// ---------------- launch ----------------
extern "C" void kernel_launch(void* const* d_in, const int* in_sizes, int n_in,
                              void* d_out, int out_size) {
    const float* base_feat = (const float*)d_in[0];
    const float* im_info   = (const float*)d_in[1];
    const float* W_conv    = (const float*)d_in[4];
    const float* b_conv    = (const float*)d_in[5];
    const float* W_cls     = (const float*)d_in[6];
    const float* b_cls     = (const float*)d_in[7];
    const float* W_bbox    = (const float*)d_in[8];
    const float* b_bbox    = (const float*)d_in[9];
    float* out = (float*)d_out;

    float *p_wh, *p_bh, *p_colc, *p_xc, *p_hc;
    int* p_nc;
    cudaGetSymbolAddress((void**)&p_wh,   g_wh);
    cudaGetSymbolAddress((void**)&p_bh,   g_bh);
    cudaGetSymbolAddress((void**)&p_colc, g_colc);
    cudaGetSymbolAddress((void**)&p_xc,   g_xc);
    cudaGetSymbolAddress((void**)&p_hc,   g_hc);
    cudaGetSymbolAddress((void**)&p_nc,   g_nc);

    cudaFuncSetAttribute(conv_emu_kernel, cudaFuncAttributeMaxDynamicSharedMemorySize, SMEM_EMU);

    prep_kernel<<<(COUT * KDIM + 255) / 256, 256>>>(W_conv, W_cls, b_cls, W_bbox, b_bbox);
    tsplit_kernel<<<BATCH * DD * HH, 256>>>(base_feat);
    {   // emu conv (implicit im2col, single-bf16 term, single-sync 5-slot pipeline)
        dim3 grid(COUT / 128, NCOL / 128);
        conv_emu_kernel<<<grid, 256, SMEM_EMU>>>(b_conv);
    }
    head18_kernel<<<NCOL / 128, 128>>>();
    escore_kernel<<<(BATCH * NPROP + 255) / 256, 256>>>();
    cutoff_kernel<<<BATCH, 1024>>>();
    flag_kernel<<<(BATCH * NPROP + 255) / 256, 256>>>();
    compact_kernel<<<1, 1024>>>();
    {
        dim3 grid(CCAP / 32, 27);
        gather_kernel<<<grid, 256>>>(base_feat);
    }
    {   // exact conv on compacted columns (32x64 tiles, R1-identical numerics)
        dim3 grid(CW / 64, COUT / 32);
        exact32x64<<<grid, 128>>>(W_conv, p_colc, p_xc, b_conv, COUT, CW, KDIM, 1, p_nc + 2);
    }
    {   // exact heads on compacted columns
        dim3 grid(CW / 64, (HROWS + 31) / 32);
        exact32x64<<<grid, 128>>>(p_wh, p_xc, p_hc, p_bh, HROWS, CW, 512, 0, p_nc + 2);
    }
    decode_cand_kernel<<<(CCAP * NANCH + 255) / 256, 256>>>(im_info);
    select_topk_kernel<<<BATCH, 1024>>>();
    {
        dim3 grid(PRE_NMS / 64, PRE_NMS / 64, BATCH);
        nms_mask_kernel<<<grid, 64>>>();
    }
    nms_scan_kernel<<<BATCH, 32>>>(out);
}